// round 5
// baseline (speedup 1.0000x reference)
#include <cuda_runtime.h>
#include <cuda_bf16.h>
#include <cstdint>

// Problem constants (GAE: GCN encoder x2 + inner-product decoder)
#define NN 50000
#define NE 1600000
#define IN_CH 256
#define HID 256
#define OUT_CH 128
#define GK 256   // K dim of both GEMMs

// ---------------- scratch (static device globals; no allocation) ----------
__device__ __align__(256) int   g_cnt[NN];
__device__ __align__(256) int   g_rowstart[NN + 1];
__device__ __align__(256) int   g_pos[NN];
__device__ __align__(256) float g_dinv[NN];
__device__ __align__(256) int   g_csr[NE];
__device__ __align__(256) float g_h1[(size_t)NN * HID];     // (x@W1) * dinv[row]
__device__ __align__(256) float g_z1[(size_t)NN * HID];     // relu(agg1*dinv + b1)
__device__ __align__(256) float g_h2[(size_t)NN * OUT_CH];  // (z1@W2) * dinv[row]
__device__ __align__(256) float g_z2[(size_t)NN * OUT_CH];  // agg2*dinv + b2

// ---------------- degree / CSR build --------------------------------------
// edge_index is staged by the harness as int32 (harness dtype set is
// {float32, int32, bfloat16}; reference int64 gets narrowed). Layout [2, E]:
// src = ei[e], dst = ei[E + e]. All index uses are bounds-guarded so a wrong
// dtype assumption degrades to a wrong answer, never a device trap.
__global__ void k_zero_cnt(int n) {
    int i = blockIdx.x * blockDim.x + threadIdx.x;
    if (i < n) g_cnt[i] = 0;
}

__global__ void k_count(const int* __restrict__ ei, int E, int n) {
    int e = blockIdx.x * blockDim.x + threadIdx.x;
    if (e < E) {
        int d = ei[(size_t)E + e];
        if ((unsigned)d < (unsigned)n) atomicAdd(&g_cnt[d], 1);
    }
}

// single-block exclusive scan over NN counts; also dinv = rsqrt(cnt+1) (self loop)
__global__ void k_scan(int n) {
    __shared__ int part[1024];
    int t = threadIdx.x;
    const int CHUNK = (NN + 1023) / 1024;
    int lo = t * CHUNK;
    int hi = lo + CHUNK; if (hi > n) hi = n;
    int s = 0;
    for (int i = lo; i < hi; i++) s += g_cnt[i];
    part[t] = s;
    __syncthreads();
    // Hillis-Steele inclusive scan
    for (int off = 1; off < 1024; off <<= 1) {
        int v = (t >= off) ? part[t - off] : 0;
        __syncthreads();
        part[t] += v;
        __syncthreads();
    }
    int base = (t == 0) ? 0 : part[t - 1];
    for (int i = lo; i < hi; i++) {
        g_rowstart[i] = base;
        g_pos[i] = base;
        g_dinv[i] = rsqrtf((float)(g_cnt[i] + 1));
        base += g_cnt[i];
    }
    if (t == 0) g_rowstart[n] = part[1023];
}

__global__ void k_fill(const int* __restrict__ ei, int E, int n) {
    int e = blockIdx.x * blockDim.x + threadIdx.x;
    if (e < E) {
        int s = ei[e];
        int d = ei[(size_t)E + e];
        if ((unsigned)s < (unsigned)n && (unsigned)d < (unsigned)n) {
            int p = atomicAdd(&g_pos[d], 1);
            if ((unsigned)p < (unsigned)NE) g_csr[p] = s;
        }
    }
}

// ---------------- tiled fp32 GEMM with dinv-row-scale epilogue -------------
// C[M, Ncols] = (A[M,256] @ B[256,Ncols]) * dinv[row]
// BM=64, BN=64, BK=16, 256 threads, 4x4 per thread.
__device__ __forceinline__ void gemm_scaled_body(
    const float* __restrict__ A, const float* __restrict__ B,
    float* __restrict__ C, int M, int Ncols)
{
    __shared__ float As[16][68];
    __shared__ float Bs[16][68];
    int tid = threadIdx.x;
    int tx = tid & 15;
    int ty = tid >> 4;
    int row0 = blockIdx.y * 64;
    int col0 = blockIdx.x * 64;

    float acc[4][4];
#pragma unroll
    for (int i = 0; i < 4; i++)
#pragma unroll
        for (int j = 0; j < 4; j++) acc[i][j] = 0.f;

    int ar = tid >> 2;           // A row within tile, 0..63
    int ak = (tid & 3) * 4;      // A k offset within tile
    int br = tid >> 4;           // B k row within tile, 0..15
    int bc = (tid & 15) * 4;     // B col within tile

    for (int k0 = 0; k0 < GK; k0 += 16) {
        float4 av;
        int arow = row0 + ar;
        if (arow < M) av = *(const float4*)(A + (size_t)arow * GK + k0 + ak);
        else av = make_float4(0.f, 0.f, 0.f, 0.f);
        As[ak + 0][ar] = av.x;
        As[ak + 1][ar] = av.y;
        As[ak + 2][ar] = av.z;
        As[ak + 3][ar] = av.w;

        float4 bv = *(const float4*)(B + (size_t)(k0 + br) * Ncols + col0 + bc);
        *(float4*)&Bs[br][bc] = bv;
        __syncthreads();

#pragma unroll
        for (int kk = 0; kk < 16; kk++) {
            float4 a4 = *(const float4*)&As[kk][ty * 4];
            float4 b4 = *(const float4*)&Bs[kk][tx * 4];
            acc[0][0] += a4.x * b4.x; acc[0][1] += a4.x * b4.y; acc[0][2] += a4.x * b4.z; acc[0][3] += a4.x * b4.w;
            acc[1][0] += a4.y * b4.x; acc[1][1] += a4.y * b4.y; acc[1][2] += a4.y * b4.z; acc[1][3] += a4.y * b4.w;
            acc[2][0] += a4.z * b4.x; acc[2][1] += a4.z * b4.y; acc[2][2] += a4.z * b4.z; acc[2][3] += a4.z * b4.w;
            acc[3][0] += a4.w * b4.x; acc[3][1] += a4.w * b4.y; acc[3][2] += a4.w * b4.z; acc[3][3] += a4.w * b4.w;
        }
        __syncthreads();
    }

#pragma unroll
    for (int i = 0; i < 4; i++) {
        int r = row0 + ty * 4 + i;
        if (r < M) {
            float s = g_dinv[r];
            float4 o = make_float4(acc[i][0] * s, acc[i][1] * s, acc[i][2] * s, acc[i][3] * s);
            *(float4*)(C + (size_t)r * Ncols + col0 + tx * 4) = o;
        }
    }
}

// wrappers: scratch destinations referenced as device symbols (device code only)
__global__ __launch_bounds__(256) void k_gemm1(
    const float* __restrict__ A, const float* __restrict__ B, int M)
{
    gemm_scaled_body(A, B, g_h1, M, HID);
}

__global__ __launch_bounds__(256) void k_gemm2(
    const float* __restrict__ B, int M)
{
    gemm_scaled_body(g_z1, B, g_h2, M, OUT_CH);
}

// ---------------- CSR aggregation: warp per node ---------------------------
// Z[node] = act( (H[node] + sum_{nbr in CSR(node)} H[nbr]) * dinv[node] + bias )
template <int COLS, bool RELU>
__device__ __forceinline__ void agg_body(
    const float* __restrict__ H, const float* __restrict__ bias,
    float* __restrict__ Z, int n)
{
    int warp = (blockIdx.x * blockDim.x + threadIdx.x) >> 5;
    if (warp >= n) return;
    int lane = threadIdx.x & 31;
    const int VPL = COLS / 128;  // float4 per lane: 2 (COLS=256) or 1 (128)

    float4 acc[VPL];
    const float4* own = (const float4*)(H + (size_t)warp * COLS);
#pragma unroll
    for (int v = 0; v < VPL; v++) acc[v] = __ldg(&own[lane + 32 * v]);

    int beg = g_rowstart[warp];
    int end = g_rowstart[warp + 1];
    for (int i = beg; i < end; i++) {
        int nb = g_csr[i];
        const float4* r = (const float4*)(H + (size_t)nb * COLS);
#pragma unroll
        for (int v = 0; v < VPL; v++) {
            float4 t = __ldg(&r[lane + 32 * v]);
            acc[v].x += t.x; acc[v].y += t.y; acc[v].z += t.z; acc[v].w += t.w;
        }
    }

    float di = g_dinv[warp];
    const float4* b4 = (const float4*)bias;
    float4* zo = (float4*)(Z + (size_t)warp * COLS);
#pragma unroll
    for (int v = 0; v < VPL; v++) {
        float4 bb = __ldg(&b4[lane + 32 * v]);
        float4 o;
        o.x = acc[v].x * di + bb.x;
        o.y = acc[v].y * di + bb.y;
        o.z = acc[v].z * di + bb.z;
        o.w = acc[v].w * di + bb.w;
        if (RELU) {
            o.x = fmaxf(o.x, 0.f); o.y = fmaxf(o.y, 0.f);
            o.z = fmaxf(o.z, 0.f); o.w = fmaxf(o.w, 0.f);
        }
        zo[lane + 32 * v] = o;
    }
}

__global__ __launch_bounds__(256) void k_agg1(const float* __restrict__ bias, int n) {
    agg_body<HID, true>(g_h1, bias, g_z1, n);
}

__global__ __launch_bounds__(256) void k_agg2(const float* __restrict__ bias, int n) {
    agg_body<OUT_CH, false>(g_h2, bias, g_z2, n);
}

// ---------------- decoder: warp per edge, dot over 128 dims ----------------
__global__ __launch_bounds__(256) void k_decode(
    const int* __restrict__ ei, float* __restrict__ out, int E, int n)
{
    int warp = (blockIdx.x * blockDim.x + threadIdx.x) >> 5;
    if (warp >= E) return;
    int lane = threadIdx.x & 31;
    int s = __ldg(&ei[warp]);
    int d = __ldg(&ei[(size_t)E + warp]);
    if ((unsigned)s >= (unsigned)n || (unsigned)d >= (unsigned)n) {
        if (lane == 0) out[warp] = 0.f;
        return;
    }
    const float4* a = (const float4*)(g_z2 + (size_t)s * OUT_CH);
    const float4* b = (const float4*)(g_z2 + (size_t)d * OUT_CH);
    float4 x = __ldg(&a[lane]);
    float4 y = __ldg(&b[lane]);
    float p = x.x * y.x + x.y * y.y + x.z * y.z + x.w * y.w;
#pragma unroll
    for (int off = 16; off > 0; off >>= 1)
        p += __shfl_down_sync(0xffffffffu, p, off);
    if (lane == 0) out[warp] = p;
}

// ---------------- launch ---------------------------------------------------
extern "C" void kernel_launch(void* const* d_in, const int* in_sizes, int n_in,
                              void* d_out, int out_size)
{
    const float* x  = (const float*)d_in[0];
    const int*   ei = (const int*)d_in[1];   // [2, E] indices, staged as int32
    const float* W1 = (const float*)d_in[2];
    const float* b1 = (const float*)d_in[3];
    const float* W2 = (const float*)d_in[4];
    const float* b2 = (const float*)d_in[5];
    float* out = (float*)d_out;

    int n = in_sizes[0] / IN_CH;    // 50000
    int E = in_sizes[1] / 2;        // 1600000

    // CSR build (dst-sorted)
    k_zero_cnt<<<(n + 255) / 256, 256>>>(n);
    k_count<<<(E + 255) / 256, 256>>>(ei, E, n);
    k_scan<<<1, 1024>>>(n);
    k_fill<<<(E + 255) / 256, 256>>>(ei, E, n);

    // layer 1: h1 = (x@W1)*dinv ; z1 = relu(agg(h1)*dinv + b1)
    {
        dim3 grid(HID / 64, (n + 63) / 64);
        k_gemm1<<<grid, 256>>>(x, W1, n);
    }
    k_agg1<<<(n * 32 + 255) / 256, 256>>>(b1, n);

    // layer 2: h2 = (z1@W2)*dinv ; z2 = agg(h2)*dinv + b2
    {
        dim3 grid(OUT_CH / 64, (n + 63) / 64);
        k_gemm2<<<grid, 256>>>(W2, n);
    }
    k_agg2<<<(n * 32 + 255) / 256, 256>>>(b2, n);

    // decode: out[e] = dot(z2[src[e]], z2[dst[e]])
    k_decode<<<(E * 32 + 255) / 256, 256>>>(ei, out, E, n);
}

// round 6
// speedup vs baseline: 1.0873x; 1.0873x over previous
#include <cuda_runtime.h>
#include <cuda_fp16.h>
#include <cstdint>

// Problem constants (GAE: GCN encoder x2 + inner-product decoder)
#define NN 50000
#define NE 1600000
#define IN_CH 256
#define HID 256
#define OUT_CH 128
#define GK 256   // K dim of both GEMMs

// ---------------- scratch (static device globals; no allocation) ----------
__device__ __align__(256) int    g_cnt[NN];
__device__ __align__(256) int    g_rowstart[NN + 1];
__device__ __align__(256) int    g_pos[NN];
__device__ __align__(256) float  g_dinv[NN];
__device__ __align__(256) int    g_csr[NE];
__device__ __align__(256) __half g_h1h[(size_t)NN * HID];     // fp16: (x@W1)*dinv[row]
__device__ __align__(256) float  g_z1[(size_t)NN * HID];      // fp32: relu(agg1*dinv+b1) (GEMM2 input)
__device__ __align__(256) __half g_h2h[(size_t)NN * OUT_CH];  // fp16: (z1@W2)*dinv[row]
__device__ __align__(256) __half g_z2h[(size_t)NN * OUT_CH];  // fp16: agg2*dinv+b2

// ---------------- degree / CSR build --------------------------------------
// edge_index staged as int32, layout [2,E]: src=ei[e], dst=ei[E+e].
__global__ void k_zero_cnt(int n) {
    int i = blockIdx.x * blockDim.x + threadIdx.x;
    if (i < n) g_cnt[i] = 0;
}

__global__ void k_count(const int* __restrict__ ei, int E, int n) {
    int e = blockIdx.x * blockDim.x + threadIdx.x;
    if (e < E) {
        int d = ei[(size_t)E + e];
        if ((unsigned)d < (unsigned)n) atomicAdd(&g_cnt[d], 1);
    }
}

__global__ void k_scan(int n) {
    __shared__ int part[1024];
    int t = threadIdx.x;
    const int CHUNK = (NN + 1023) / 1024;
    int lo = t * CHUNK;
    int hi = lo + CHUNK; if (hi > n) hi = n;
    int s = 0;
    for (int i = lo; i < hi; i++) s += g_cnt[i];
    part[t] = s;
    __syncthreads();
    for (int off = 1; off < 1024; off <<= 1) {
        int v = (t >= off) ? part[t - off] : 0;
        __syncthreads();
        part[t] += v;
        __syncthreads();
    }
    int base = (t == 0) ? 0 : part[t - 1];
    for (int i = lo; i < hi; i++) {
        g_rowstart[i] = base;
        g_pos[i] = base;
        g_dinv[i] = rsqrtf((float)(g_cnt[i] + 1));
        base += g_cnt[i];
    }
    if (t == 0) g_rowstart[n] = part[1023];
}

__global__ void k_fill(const int* __restrict__ ei, int E, int n) {
    int e = blockIdx.x * blockDim.x + threadIdx.x;
    if (e < E) {
        int s = ei[e];
        int d = ei[(size_t)E + e];
        if ((unsigned)s < (unsigned)n && (unsigned)d < (unsigned)n) {
            int p = atomicAdd(&g_pos[d], 1);
            if ((unsigned)p < (unsigned)NE) g_csr[p] = s;
        }
    }
}

// ---------------- tiled fp32 GEMM, fp16 output with dinv-row-scale --------
// C16[M, Ncols] = half( (A[M,256] @ B[256,Ncols]) * dinv[row] )
// BM=64, BN=64, BK=16, 256 threads, 4x4 per thread.
__device__ __forceinline__ void gemm_scaled_body_h(
    const float* __restrict__ A, const float* __restrict__ B,
    __half* __restrict__ C16, int M, int Ncols)
{
    __shared__ float As[16][68];
    __shared__ float Bs[16][68];
    int tid = threadIdx.x;
    int tx = tid & 15;
    int ty = tid >> 4;
    int row0 = blockIdx.y * 64;
    int col0 = blockIdx.x * 64;

    float acc[4][4];
#pragma unroll
    for (int i = 0; i < 4; i++)
#pragma unroll
        for (int j = 0; j < 4; j++) acc[i][j] = 0.f;

    int ar = tid >> 2;           // A row within tile, 0..63
    int ak = (tid & 3) * 4;      // A k offset within tile
    int br = tid >> 4;           // B k row within tile, 0..15
    int bc = (tid & 15) * 4;     // B col within tile

    for (int k0 = 0; k0 < GK; k0 += 16) {
        float4 av;
        int arow = row0 + ar;
        if (arow < M) av = *(const float4*)(A + (size_t)arow * GK + k0 + ak);
        else av = make_float4(0.f, 0.f, 0.f, 0.f);
        As[ak + 0][ar] = av.x;
        As[ak + 1][ar] = av.y;
        As[ak + 2][ar] = av.z;
        As[ak + 3][ar] = av.w;

        float4 bv = *(const float4*)(B + (size_t)(k0 + br) * Ncols + col0 + bc);
        *(float4*)&Bs[br][bc] = bv;
        __syncthreads();

#pragma unroll
        for (int kk = 0; kk < 16; kk++) {
            float4 a4 = *(const float4*)&As[kk][ty * 4];
            float4 b4 = *(const float4*)&Bs[kk][tx * 4];
            acc[0][0] += a4.x * b4.x; acc[0][1] += a4.x * b4.y; acc[0][2] += a4.x * b4.z; acc[0][3] += a4.x * b4.w;
            acc[1][0] += a4.y * b4.x; acc[1][1] += a4.y * b4.y; acc[1][2] += a4.y * b4.z; acc[1][3] += a4.y * b4.w;
            acc[2][0] += a4.z * b4.x; acc[2][1] += a4.z * b4.y; acc[2][2] += a4.z * b4.z; acc[2][3] += a4.z * b4.w;
            acc[3][0] += a4.w * b4.x; acc[3][1] += a4.w * b4.y; acc[3][2] += a4.w * b4.z; acc[3][3] += a4.w * b4.w;
        }
        __syncthreads();
    }

#pragma unroll
    for (int i = 0; i < 4; i++) {
        int r = row0 + ty * 4 + i;
        if (r < M) {
            float s = g_dinv[r];
            __half2 lo = __floats2half2_rn(acc[i][0] * s, acc[i][1] * s);
            __half2 hi = __floats2half2_rn(acc[i][2] * s, acc[i][3] * s);
            uint2 o;
            o.x = *(unsigned*)&lo;
            o.y = *(unsigned*)&hi;
            *(uint2*)(C16 + (size_t)r * Ncols + col0 + tx * 4) = o;
        }
    }
}

__global__ __launch_bounds__(256) void k_gemm1(
    const float* __restrict__ A, const float* __restrict__ B, int M)
{
    gemm_scaled_body_h(A, B, g_h1h, M, HID);
}

__global__ __launch_bounds__(256) void k_gemm2(
    const float* __restrict__ B, int M)
{
    gemm_scaled_body_h(g_z1, B, g_h2h, M, OUT_CH);
}

// ---------------- CSR aggregation (fp16 gather, fp32 accumulate) ----------
// agg1: z1(fp32) = relu((h1h[node] + sum_nbr h1h[nbr]) * dinv + b1),  COLS=256
// one warp per node; each lane owns 8 contiguous halves (one uint4).
__global__ __launch_bounds__(256) void k_agg1(const float* __restrict__ bias, int n)
{
    int node = (blockIdx.x * blockDim.x + threadIdx.x) >> 5;
    if (node >= n) return;
    int lane = threadIdx.x & 31;

    float acc[8];
    {
        uint4 v = __ldg((const uint4*)(g_h1h + (size_t)node * HID) + lane);
        const __half2* p = (const __half2*)&v;
#pragma unroll
        for (int j = 0; j < 4; j++) {
            float2 f = __half22float2(p[j]);
            acc[2 * j] = f.x; acc[2 * j + 1] = f.y;
        }
    }

    int beg = g_rowstart[node];
    int end = g_rowstart[node + 1];
    for (int i = beg; i < end; i++) {
        int nb = g_csr[i];
        uint4 v = __ldg((const uint4*)(g_h1h + (size_t)nb * HID) + lane);
        const __half2* p = (const __half2*)&v;
#pragma unroll
        for (int j = 0; j < 4; j++) {
            float2 f = __half22float2(p[j]);
            acc[2 * j] += f.x; acc[2 * j + 1] += f.y;
        }
    }

    float di = g_dinv[node];
    float4 b0 = __ldg((const float4*)bias + lane * 2);
    float4 b1v = __ldg((const float4*)bias + lane * 2 + 1);
    float4 o0, o1;
    o0.x = fmaxf(acc[0] * di + b0.x, 0.f);
    o0.y = fmaxf(acc[1] * di + b0.y, 0.f);
    o0.z = fmaxf(acc[2] * di + b0.z, 0.f);
    o0.w = fmaxf(acc[3] * di + b0.w, 0.f);
    o1.x = fmaxf(acc[4] * di + b1v.x, 0.f);
    o1.y = fmaxf(acc[5] * di + b1v.y, 0.f);
    o1.z = fmaxf(acc[6] * di + b1v.z, 0.f);
    o1.w = fmaxf(acc[7] * di + b1v.w, 0.f);
    float4* zo = (float4*)(g_z1 + (size_t)node * HID);
    zo[lane * 2] = o0;
    zo[lane * 2 + 1] = o1;
}

// agg2: z2h(fp16) = (h2h[node] + sum_nbr h2h[nbr]) * dinv + b2,  COLS=128
// one warp per node; each lane owns 4 contiguous halves (one uint2).
__global__ __launch_bounds__(256) void k_agg2(const float* __restrict__ bias, int n)
{
    int node = (blockIdx.x * blockDim.x + threadIdx.x) >> 5;
    if (node >= n) return;
    int lane = threadIdx.x & 31;

    float acc[4];
    {
        uint2 v = __ldg((const uint2*)(g_h2h + (size_t)node * OUT_CH) + lane);
        const __half2* p = (const __half2*)&v;
        float2 f0 = __half22float2(p[0]);
        float2 f1 = __half22float2(p[1]);
        acc[0] = f0.x; acc[1] = f0.y; acc[2] = f1.x; acc[3] = f1.y;
    }

    int beg = g_rowstart[node];
    int end = g_rowstart[node + 1];
    for (int i = beg; i < end; i++) {
        int nb = g_csr[i];
        uint2 v = __ldg((const uint2*)(g_h2h + (size_t)nb * OUT_CH) + lane);
        const __half2* p = (const __half2*)&v;
        float2 f0 = __half22float2(p[0]);
        float2 f1 = __half22float2(p[1]);
        acc[0] += f0.x; acc[1] += f0.y; acc[2] += f1.x; acc[3] += f1.y;
    }

    float di = g_dinv[node];
    float4 bb = __ldg((const float4*)bias + lane);
    __half2 lo = __floats2half2_rn(acc[0] * di + bb.x, acc[1] * di + bb.y);
    __half2 hi = __floats2half2_rn(acc[2] * di + bb.z, acc[3] * di + bb.w);
    uint2 o;
    o.x = *(unsigned*)&lo;
    o.y = *(unsigned*)&hi;
    *((uint2*)(g_z2h + (size_t)node * OUT_CH) + lane) = o;
}

// ---------------- decoder: warp per edge, fp16 rows, fp32 dot --------------
__global__ __launch_bounds__(256) void k_decode(
    const int* __restrict__ ei, float* __restrict__ out, int E, int n)
{
    int warp = (blockIdx.x * blockDim.x + threadIdx.x) >> 5;
    if (warp >= E) return;
    int lane = threadIdx.x & 31;
    int s = __ldg(&ei[warp]);
    int d = __ldg(&ei[(size_t)E + warp]);
    if ((unsigned)s >= (unsigned)n || (unsigned)d >= (unsigned)n) {
        if (lane == 0) out[warp] = 0.f;
        return;
    }
    uint2 va = __ldg((const uint2*)(g_z2h + (size_t)s * OUT_CH) + lane);
    uint2 vb = __ldg((const uint2*)(g_z2h + (size_t)d * OUT_CH) + lane);
    const __half2* pa = (const __half2*)&va;
    const __half2* pb = (const __half2*)&vb;
    float2 a0 = __half22float2(pa[0]), a1 = __half22float2(pa[1]);
    float2 b0 = __half22float2(pb[0]), b1 = __half22float2(pb[1]);
    float p = a0.x * b0.x + a0.y * b0.y + a1.x * b1.x + a1.y * b1.y;
#pragma unroll
    for (int off = 16; off > 0; off >>= 1)
        p += __shfl_down_sync(0xffffffffu, p, off);
    if (lane == 0) out[warp] = p;
}

// ---------------- launch ---------------------------------------------------
extern "C" void kernel_launch(void* const* d_in, const int* in_sizes, int n_in,
                              void* d_out, int out_size)
{
    const float* x  = (const float*)d_in[0];
    const int*   ei = (const int*)d_in[1];   // [2, E] indices, staged as int32
    const float* W1 = (const float*)d_in[2];
    const float* b1 = (const float*)d_in[3];
    const float* W2 = (const float*)d_in[4];
    const float* b2 = (const float*)d_in[5];
    float* out = (float*)d_out;

    int n = in_sizes[0] / IN_CH;    // 50000
    int E = in_sizes[1] / 2;        // 1600000

    // CSR build (dst-sorted)
    k_zero_cnt<<<(n + 255) / 256, 256>>>(n);
    k_count<<<(E + 255) / 256, 256>>>(ei, E, n);
    k_scan<<<1, 1024>>>(n);
    k_fill<<<(E + 255) / 256, 256>>>(ei, E, n);

    // layer 1: h1h = half((x@W1)*dinv) ; z1 = relu(agg(h1h)*dinv + b1) [fp32]
    {
        dim3 grid(HID / 64, (n + 63) / 64);
        k_gemm1<<<grid, 256>>>(x, W1, n);
    }
    k_agg1<<<(n * 32 + 255) / 256, 256>>>(b1, n);

    // layer 2: h2h = half((z1@W2)*dinv) ; z2h = half(agg(h2h)*dinv + b2)
    {
        dim3 grid(OUT_CH / 64, (n + 63) / 64);
        k_gemm2<<<grid, 256>>>(W2, n);
    }
    k_agg2<<<(n * 32 + 255) / 256, 256>>>(b2, n);

    // decode: out[e] = dot(z2[src[e]], z2[dst[e]])
    k_decode<<<(E * 32 + 255) / 256, 256>>>(ei, out, E, n);
}

// round 7
// speedup vs baseline: 1.4915x; 1.3718x over previous
#include <cuda_runtime.h>
#include <cuda_fp16.h>
#include <mma.h>
#include <cstdint>

using namespace nvcuda;

// Problem constants (GAE: GCN encoder x2 + inner-product decoder)
#define NN 50000
#define NE 1600000
#define IN_CH 256
#define HID 256
#define OUT_CH 128
#define GK 256   // K dim of both GEMMs

// ---------------- scratch (static device globals; no allocation) ----------
__device__ __align__(256) int    g_cnt[NN];
__device__ __align__(256) int    g_rowstart[NN + 1];
__device__ __align__(256) int    g_pos[NN];
__device__ __align__(256) float  g_dinv[NN];
__device__ __align__(256) int    g_csr[NE];
__device__ __align__(256) __half g_xh[(size_t)NN * IN_CH];    // fp16: x * dinv[row]
__device__ __align__(256) __half g_w1h[GK * HID];             // fp16 W1
__device__ __align__(256) __half g_w2h[GK * OUT_CH];          // fp16 W2
__device__ __align__(256) __half g_h1h[(size_t)NN * HID];     // fp16: (x*dinv)@W1
__device__ __align__(256) __half g_z1h[(size_t)NN * HID];     // fp16: relu(agg*di+b1)*di
__device__ __align__(256) __half g_h2h[(size_t)NN * OUT_CH];  // fp16: z1h@W2
__device__ __align__(256) __half g_z2h[(size_t)NN * OUT_CH];  // fp16: agg*di+b2

// ---------------- degree / CSR build --------------------------------------
// edge_index staged as int32, layout [2,E]: src=ei[e], dst=ei[E+e].
__global__ void k_zero_cnt(int n) {
    int i = blockIdx.x * blockDim.x + threadIdx.x;
    if (i < n) g_cnt[i] = 0;
}

__global__ void k_count(const int* __restrict__ ei, int E, int n) {
    int e = blockIdx.x * blockDim.x + threadIdx.x;
    if (e < E) {
        int d = ei[(size_t)E + e];
        if ((unsigned)d < (unsigned)n) atomicAdd(&g_cnt[d], 1);
    }
}

__global__ void k_scan(int n) {
    __shared__ int part[1024];
    int t = threadIdx.x;
    const int CHUNK = (NN + 1023) / 1024;
    int lo = t * CHUNK;
    int hi = lo + CHUNK; if (hi > n) hi = n;
    int s = 0;
    for (int i = lo; i < hi; i++) s += g_cnt[i];
    part[t] = s;
    __syncthreads();
    for (int off = 1; off < 1024; off <<= 1) {
        int v = (t >= off) ? part[t - off] : 0;
        __syncthreads();
        part[t] += v;
        __syncthreads();
    }
    int base = (t == 0) ? 0 : part[t - 1];
    for (int i = lo; i < hi; i++) {
        g_rowstart[i] = base;
        g_pos[i] = base;
        g_dinv[i] = rsqrtf((float)(g_cnt[i] + 1));
        base += g_cnt[i];
    }
    if (t == 0) g_rowstart[n] = part[1023];
}

__global__ void k_fill(const int* __restrict__ ei, int E, int n) {
    int e = blockIdx.x * blockDim.x + threadIdx.x;
    if (e < E) {
        int s = ei[e];
        int d = ei[(size_t)E + e];
        if ((unsigned)s < (unsigned)n && (unsigned)d < (unsigned)n) {
            int p = atomicAdd(&g_pos[d], 1);
            if ((unsigned)p < (unsigned)NE) g_csr[p] = s;
        }
    }
}

// ---------------- conversions ----------------------------------------------
// xh[row, :] = half(x[row, :] * dinv[row])   (row-scale commutes with @W)
__global__ void k_cvt_x(const float* __restrict__ x, int n) {
    int i = blockIdx.x * blockDim.x + threadIdx.x;      // one float4 per thread
    int total = n * (IN_CH / 4);
    if (i >= total) return;
    int row = i / (IN_CH / 4);
    float di = g_dinv[row];
    float4 v = __ldg((const float4*)x + i);
    __half2 lo = __floats2half2_rn(v.x * di, v.y * di);
    __half2 hi = __floats2half2_rn(v.z * di, v.w * di);
    uint2 o; o.x = *(unsigned*)&lo; o.y = *(unsigned*)&hi;
    *((uint2*)g_xh + i) = o;
}

__device__ __forceinline__ void cvt_w_body(const float* __restrict__ W,
                                           __half* __restrict__ Wh, int count4) {
    int i = blockIdx.x * blockDim.x + threadIdx.x;
    if (i >= count4) return;
    float4 v = __ldg((const float4*)W + i);
    __half2 lo = __floats2half2_rn(v.x, v.y);
    __half2 hi = __floats2half2_rn(v.z, v.w);
    uint2 o; o.x = *(unsigned*)&lo; o.y = *(unsigned*)&hi;
    *((uint2*)Wh + i) = o;
}

__global__ void k_cvt_w1(const float* __restrict__ W) { cvt_w_body(W, g_w1h, GK * HID / 4); }
__global__ void k_cvt_w2(const float* __restrict__ W) { cvt_w_body(W, g_w2h, GK * OUT_CH / 4); }

// ---------------- wmma fp16 GEMM: C = A[M,256] @ B[256,Ncols] --------------
// BM=128, BN=64, BK=32; 256 threads = 8 warps in 4x2; each warp 32x32 (2x2 frags).
#define BM 128
#define BN 64
#define BK 32
#define A_LD 40   // BK + 8 pad (halves)
#define B_LD 72   // BN + 8 pad (halves)
#define C_LD 68   // BN + 4 pad (floats)

__device__ __forceinline__ void gemm_wmma_body(
    const __half* __restrict__ A, const __half* __restrict__ B,
    __half* __restrict__ C, int M, int Ncols)
{
    __shared__ __align__(16) char sm[BM * C_LD * 4];   // 34816 B; unioned A/B vs C
    __half* As = (__half*)sm;                          // [BM][A_LD]
    __half* Bs = As + BM * A_LD;                       // [BK][B_LD]
    float*  Cs = (float*)sm;                           // [BM][C_LD]

    int tid = threadIdx.x;
    int warp = tid >> 5;
    int wrow = warp >> 1;          // 0..3  -> 32-row band
    int wcol = warp & 1;           // 0..1  -> 32-col band
    int row0 = blockIdx.y * BM;
    int col0 = blockIdx.x * BN;

    wmma::fragment<wmma::accumulator, 16, 16, 16, float> c[2][2];
#pragma unroll
    for (int i = 0; i < 2; i++)
#pragma unroll
        for (int j = 0; j < 2; j++) wmma::fill_fragment(c[i][j], 0.f);

    for (int k0 = 0; k0 < GK; k0 += BK) {
        // load A tile: BM x BK halves, 2 uint4 per thread
#pragma unroll
        for (int t = 0; t < 2; t++) {
            int v = tid + t * 256;          // 0..511
            int r = v >> 2;                 // 0..127
            int kc = (v & 3) * 8;           // 0,8,16,24
            int grow = row0 + r;
            uint4 val = make_uint4(0u, 0u, 0u, 0u);
            if (grow < M)
                val = *(const uint4*)(A + (size_t)grow * GK + k0 + kc);
            *(uint4*)(As + r * A_LD + kc) = val;
        }
        // load B tile: BK x BN halves, 1 uint4 per thread
        {
            int r = tid >> 3;               // 0..31
            int c8 = (tid & 7) * 8;         // 0..56
            uint4 val = *(const uint4*)(B + (size_t)(k0 + r) * Ncols + col0 + c8);
            *(uint4*)(Bs + r * B_LD + c8) = val;
        }
        __syncthreads();

#pragma unroll
        for (int kk = 0; kk < BK; kk += 16) {
            wmma::fragment<wmma::matrix_a, 16, 16, 16, __half, wmma::row_major> a[2];
            wmma::fragment<wmma::matrix_b, 16, 16, 16, __half, wmma::row_major> b[2];
#pragma unroll
            for (int i = 0; i < 2; i++)
                wmma::load_matrix_sync(a[i], As + (wrow * 32 + i * 16) * A_LD + kk, A_LD);
#pragma unroll
            for (int j = 0; j < 2; j++)
                wmma::load_matrix_sync(b[j], Bs + kk * B_LD + wcol * 32 + j * 16, B_LD);
#pragma unroll
            for (int i = 0; i < 2; i++)
#pragma unroll
                for (int j = 0; j < 2; j++)
                    wmma::mma_sync(c[i][j], a[i], b[j], c[i][j]);
        }
        __syncthreads();
    }

    // stage fp32 result in smem, convert to fp16, write out
#pragma unroll
    for (int i = 0; i < 2; i++)
#pragma unroll
        for (int j = 0; j < 2; j++)
            wmma::store_matrix_sync(Cs + (wrow * 32 + i * 16) * C_LD + wcol * 32 + j * 16,
                                    c[i][j], C_LD, wmma::mem_row_major);
    __syncthreads();

    if (tid < BM) {
        int grow = row0 + tid;
        if (grow < M) {
            const float* src = Cs + tid * C_LD;
            __half* dst = C + (size_t)grow * Ncols + col0;
#pragma unroll
            for (int cB = 0; cB < BN; cB += 8) {
                __half2 p0 = __floats2half2_rn(src[cB + 0], src[cB + 1]);
                __half2 p1 = __floats2half2_rn(src[cB + 2], src[cB + 3]);
                __half2 p2 = __floats2half2_rn(src[cB + 4], src[cB + 5]);
                __half2 p3 = __floats2half2_rn(src[cB + 6], src[cB + 7]);
                uint4 o;
                o.x = *(unsigned*)&p0; o.y = *(unsigned*)&p1;
                o.z = *(unsigned*)&p2; o.w = *(unsigned*)&p3;
                *(uint4*)(dst + cB) = o;
            }
        }
    }
}

__global__ __launch_bounds__(256) void k_gemm1(int M) {
    gemm_wmma_body(g_xh, g_w1h, g_h1h, M, HID);
}

__global__ __launch_bounds__(256) void k_gemm2(int M) {
    gemm_wmma_body(g_z1h, g_w2h, g_h2h, M, OUT_CH);
}

// ---------------- CSR aggregation (fp16 gather, fp32 accumulate) ----------
// agg1: z1h = half( relu((h1h[node] + sum_nbr h1h[nbr]) * di + b1) * di )
__global__ __launch_bounds__(256) void k_agg1(const float* __restrict__ bias, int n)
{
    int node = (blockIdx.x * blockDim.x + threadIdx.x) >> 5;
    if (node >= n) return;
    int lane = threadIdx.x & 31;

    float acc[8];
    {
        uint4 v = __ldg((const uint4*)(g_h1h + (size_t)node * HID) + lane);
        const __half2* p = (const __half2*)&v;
#pragma unroll
        for (int j = 0; j < 4; j++) {
            float2 f = __half22float2(p[j]);
            acc[2 * j] = f.x; acc[2 * j + 1] = f.y;
        }
    }

    int beg = g_rowstart[node];
    int end = g_rowstart[node + 1];
    for (int i = beg; i < end; i++) {
        int nb = g_csr[i];
        uint4 v = __ldg((const uint4*)(g_h1h + (size_t)nb * HID) + lane);
        const __half2* p = (const __half2*)&v;
#pragma unroll
        for (int j = 0; j < 4; j++) {
            float2 f = __half22float2(p[j]);
            acc[2 * j] += f.x; acc[2 * j + 1] += f.y;
        }
    }

    float di = g_dinv[node];
    float4 b0 = __ldg((const float4*)bias + lane * 2);
    float4 b1v = __ldg((const float4*)bias + lane * 2 + 1);
    float o[8];
    o[0] = fmaxf(acc[0] * di + b0.x, 0.f) * di;
    o[1] = fmaxf(acc[1] * di + b0.y, 0.f) * di;
    o[2] = fmaxf(acc[2] * di + b0.z, 0.f) * di;
    o[3] = fmaxf(acc[3] * di + b0.w, 0.f) * di;
    o[4] = fmaxf(acc[4] * di + b1v.x, 0.f) * di;
    o[5] = fmaxf(acc[5] * di + b1v.y, 0.f) * di;
    o[6] = fmaxf(acc[6] * di + b1v.z, 0.f) * di;
    o[7] = fmaxf(acc[7] * di + b1v.w, 0.f) * di;
    __half2 h0 = __floats2half2_rn(o[0], o[1]);
    __half2 h1 = __floats2half2_rn(o[2], o[3]);
    __half2 h2 = __floats2half2_rn(o[4], o[5]);
    __half2 h3 = __floats2half2_rn(o[6], o[7]);
    uint4 ov;
    ov.x = *(unsigned*)&h0; ov.y = *(unsigned*)&h1;
    ov.z = *(unsigned*)&h2; ov.w = *(unsigned*)&h3;
    *((uint4*)(g_z1h + (size_t)node * HID) + lane) = ov;
}

// agg2: z2h = half((h2h[node] + sum_nbr h2h[nbr]) * di + b2)
__global__ __launch_bounds__(256) void k_agg2(const float* __restrict__ bias, int n)
{
    int node = (blockIdx.x * blockDim.x + threadIdx.x) >> 5;
    if (node >= n) return;
    int lane = threadIdx.x & 31;

    float acc[4];
    {
        uint2 v = __ldg((const uint2*)(g_h2h + (size_t)node * OUT_CH) + lane);
        const __half2* p = (const __half2*)&v;
        float2 f0 = __half22float2(p[0]);
        float2 f1 = __half22float2(p[1]);
        acc[0] = f0.x; acc[1] = f0.y; acc[2] = f1.x; acc[3] = f1.y;
    }

    int beg = g_rowstart[node];
    int end = g_rowstart[node + 1];
    for (int i = beg; i < end; i++) {
        int nb = g_csr[i];
        uint2 v = __ldg((const uint2*)(g_h2h + (size_t)nb * OUT_CH) + lane);
        const __half2* p = (const __half2*)&v;
        float2 f0 = __half22float2(p[0]);
        float2 f1 = __half22float2(p[1]);
        acc[0] += f0.x; acc[1] += f0.y; acc[2] += f1.x; acc[3] += f1.y;
    }

    float di = g_dinv[node];
    float4 bb = __ldg((const float4*)bias + lane);
    __half2 lo = __floats2half2_rn(acc[0] * di + bb.x, acc[1] * di + bb.y);
    __half2 hi = __floats2half2_rn(acc[2] * di + bb.z, acc[3] * di + bb.w);
    uint2 o;
    o.x = *(unsigned*)&lo;
    o.y = *(unsigned*)&hi;
    *((uint2*)(g_z2h + (size_t)node * OUT_CH) + lane) = o;
}

// ---------------- decoder: warp per edge, fp16 rows, fp32 dot --------------
__global__ __launch_bounds__(256) void k_decode(
    const int* __restrict__ ei, float* __restrict__ out, int E, int n)
{
    int warp = (blockIdx.x * blockDim.x + threadIdx.x) >> 5;
    if (warp >= E) return;
    int lane = threadIdx.x & 31;
    int s = __ldg(&ei[warp]);
    int d = __ldg(&ei[(size_t)E + warp]);
    if ((unsigned)s >= (unsigned)n || (unsigned)d >= (unsigned)n) {
        if (lane == 0) out[warp] = 0.f;
        return;
    }
    uint2 va = __ldg((const uint2*)(g_z2h + (size_t)s * OUT_CH) + lane);
    uint2 vb = __ldg((const uint2*)(g_z2h + (size_t)d * OUT_CH) + lane);
    const __half2* pa = (const __half2*)&va;
    const __half2* pb = (const __half2*)&vb;
    float2 a0 = __half22float2(pa[0]), a1 = __half22float2(pa[1]);
    float2 b0 = __half22float2(pb[0]), b1 = __half22float2(pb[1]);
    float p = a0.x * b0.x + a0.y * b0.y + a1.x * b1.x + a1.y * b1.y;
#pragma unroll
    for (int off = 16; off > 0; off >>= 1)
        p += __shfl_down_sync(0xffffffffu, p, off);
    if (lane == 0) out[warp] = p;
}

// ---------------- launch ---------------------------------------------------
extern "C" void kernel_launch(void* const* d_in, const int* in_sizes, int n_in,
                              void* d_out, int out_size)
{
    const float* x  = (const float*)d_in[0];
    const int*   ei = (const int*)d_in[1];   // [2, E] indices, staged as int32
    const float* W1 = (const float*)d_in[2];
    const float* b1 = (const float*)d_in[3];
    const float* W2 = (const float*)d_in[4];
    const float* b2 = (const float*)d_in[5];
    float* out = (float*)d_out;

    int n = in_sizes[0] / IN_CH;    // 50000
    int E = in_sizes[1] / 2;        // 1600000

    // CSR build (dst-sorted)
    k_zero_cnt<<<(n + 255) / 256, 256>>>(n);
    k_count<<<(E + 255) / 256, 256>>>(ei, E, n);
    k_scan<<<1, 1024>>>(n);
    k_fill<<<(E + 255) / 256, 256>>>(ei, E, n);

    // fp16 conversions (x scaled by dinv; weights plain)
    k_cvt_x<<<(n * (IN_CH / 4) + 255) / 256, 256>>>(x, n);
    k_cvt_w1<<<(GK * HID / 4 + 255) / 256, 256>>>(W1);
    k_cvt_w2<<<(GK * OUT_CH / 4 + 255) / 256, 256>>>(W2);

    // layer 1: h1h = xh@W1 ; z1h = relu(agg*di+b1)*di
    {
        dim3 grid(HID / BN, (n + BM - 1) / BM);
        k_gemm1<<<grid, 256>>>(n);
    }
    k_agg1<<<(n * 32 + 255) / 256, 256>>>(b1, n);

    // layer 2: h2h = z1h@W2 ; z2h = agg*di + b2
    {
        dim3 grid(OUT_CH / BN, (n + BM - 1) / BM);
        k_gemm2<<<grid, 256>>>(n);
    }
    k_agg2<<<(n * 32 + 255) / 256, 256>>>(b2, n);

    // decode: out[e] = dot(z2[src[e]], z2[dst[e]])
    k_decode<<<(E * 32 + 255) / 256, 256>>>(ei, out, E, n);
}

// round 8
// speedup vs baseline: 1.5672x; 1.0508x over previous
#include <cuda_runtime.h>
#include <cuda_fp16.h>
#include <mma.h>
#include <cstdint>

using namespace nvcuda;

// Problem constants (GAE: GCN encoder x2 + inner-product decoder)
#define NN 50000
#define NE 1600000
#define IN_CH 256
#define HID 256
#define OUT_CH 128
#define GK 256   // K dim of both GEMMs

// ---------------- scratch (static device globals; no allocation) ----------
__device__ __align__(256) int    g_cnt[NN];
__device__ __align__(256) int    g_rowstart[NN + 1];
__device__ __align__(256) int    g_pos[NN];
__device__ __align__(256) float  g_dinv[NN];
__device__ __align__(256) int    g_csr[NE];
__device__ __align__(256) __half g_xh[(size_t)NN * IN_CH];    // fp16 x (UNSCALED)
__device__ __align__(256) __half g_w1h[GK * HID];             // fp16 W1
__device__ __align__(256) __half g_w2h[GK * OUT_CH];          // fp16 W2
__device__ __align__(256) __half g_h1h[(size_t)NN * HID];     // fp16: x@W1
__device__ __align__(256) __half g_z1h[(size_t)NN * HID];     // fp16: z1 (unscaled)
__device__ __align__(256) __half g_h2h[(size_t)NN * OUT_CH];  // fp16: z1@W2
__device__ __align__(256) __half g_z2h[(size_t)NN * OUT_CH];  // fp16: z2

// ---------------- degree / CSR build --------------------------------------
// edge_index staged as int32, layout [2,E]: src=ei[e], dst=ei[E+e].
__global__ void k_zero_cnt(int n) {
    int i = blockIdx.x * blockDim.x + threadIdx.x;
    if (i < n) g_cnt[i] = 0;
}

__global__ void k_count(const int* __restrict__ ei, int E, int n) {
    int e = blockIdx.x * blockDim.x + threadIdx.x;
    if (e < E) {
        int d = ei[(size_t)E + e];
        if ((unsigned)d < (unsigned)n) atomicAdd(&g_cnt[d], 1);
    }
}

__global__ void k_scan(int n) {
    __shared__ int part[1024];
    int t = threadIdx.x;
    const int CHUNK = (NN + 1023) / 1024;
    int lo = t * CHUNK;
    int hi = lo + CHUNK; if (hi > n) hi = n;
    int s = 0;
    for (int i = lo; i < hi; i++) s += g_cnt[i];
    part[t] = s;
    __syncthreads();
    for (int off = 1; off < 1024; off <<= 1) {
        int v = (t >= off) ? part[t - off] : 0;
        __syncthreads();
        part[t] += v;
        __syncthreads();
    }
    int base = (t == 0) ? 0 : part[t - 1];
    for (int i = lo; i < hi; i++) {
        g_rowstart[i] = base;
        g_pos[i] = base;
        g_dinv[i] = rsqrtf((float)(g_cnt[i] + 1));
        base += g_cnt[i];
    }
    if (t == 0) g_rowstart[n] = part[1023];
}

__global__ void k_fill(const int* __restrict__ ei, int E, int n) {
    int e = blockIdx.x * blockDim.x + threadIdx.x;
    if (e < E) {
        int s = ei[e];
        int d = ei[(size_t)E + e];
        if ((unsigned)s < (unsigned)n && (unsigned)d < (unsigned)n) {
            int p = atomicAdd(&g_pos[d], 1);
            if ((unsigned)p < (unsigned)NE) g_csr[p] = s;
        }
    }
}

// ---------------- conversions (no dinv dependency -> overlappable) --------
__device__ __forceinline__ void cvt_body(const float* __restrict__ S,
                                         __half* __restrict__ D, int count4) {
    int i = blockIdx.x * blockDim.x + threadIdx.x;
    if (i >= count4) return;
    float4 v = __ldg((const float4*)S + i);
    __half2 lo = __floats2half2_rn(v.x, v.y);
    __half2 hi = __floats2half2_rn(v.z, v.w);
    uint2 o; o.x = *(unsigned*)&lo; o.y = *(unsigned*)&hi;
    *((uint2*)D + i) = o;
}

__global__ void k_cvt_x(const float* __restrict__ x, int n) { cvt_body(x, g_xh, n * (IN_CH / 4)); }
__global__ void k_cvt_w1(const float* __restrict__ W) { cvt_body(W, g_w1h, GK * HID / 4); }
__global__ void k_cvt_w2(const float* __restrict__ W) { cvt_body(W, g_w2h, GK * OUT_CH / 4); }

// ---------------- wmma fp16 GEMM: C = A[M,256] @ B[256,Ncols] --------------
// BM=128, BN=64, BK=32; 256 threads = 8 warps in 4x2; each warp 32x32 (2x2 frags).
#define BM 128
#define BN 64
#define BK 32
#define A_LD 40   // BK + 8 pad (halves)
#define B_LD 72   // BN + 8 pad (halves)
#define C_LD 68   // BN + 4 pad (floats)

__device__ __forceinline__ void gemm_wmma_body(
    const __half* __restrict__ A, const __half* __restrict__ B,
    __half* __restrict__ C, int M, int Ncols)
{
    __shared__ __align__(16) char sm[BM * C_LD * 4];   // 34816 B; unioned A/B vs C
    __half* As = (__half*)sm;                          // [BM][A_LD]
    __half* Bs = As + BM * A_LD;                       // [BK][B_LD]
    float*  Cs = (float*)sm;                           // [BM][C_LD]

    int tid = threadIdx.x;
    int warp = tid >> 5;
    int wrow = warp >> 1;          // 0..3  -> 32-row band
    int wcol = warp & 1;           // 0..1  -> 32-col band
    int row0 = blockIdx.y * BM;
    int col0 = blockIdx.x * BN;

    wmma::fragment<wmma::accumulator, 16, 16, 16, float> c[2][2];
#pragma unroll
    for (int i = 0; i < 2; i++)
#pragma unroll
        for (int j = 0; j < 2; j++) wmma::fill_fragment(c[i][j], 0.f);

    for (int k0 = 0; k0 < GK; k0 += BK) {
        // load A tile: BM x BK halves, 2 uint4 per thread
#pragma unroll
        for (int t = 0; t < 2; t++) {
            int v = tid + t * 256;          // 0..511
            int r = v >> 2;                 // 0..127
            int kc = (v & 3) * 8;           // 0,8,16,24
            int grow = row0 + r;
            uint4 val = make_uint4(0u, 0u, 0u, 0u);
            if (grow < M)
                val = *(const uint4*)(A + (size_t)grow * GK + k0 + kc);
            *(uint4*)(As + r * A_LD + kc) = val;
        }
        // load B tile: BK x BN halves, 1 uint4 per thread
        {
            int r = tid >> 3;               // 0..31
            int c8 = (tid & 7) * 8;         // 0..56
            uint4 val = *(const uint4*)(B + (size_t)(k0 + r) * Ncols + col0 + c8);
            *(uint4*)(Bs + r * B_LD + c8) = val;
        }
        __syncthreads();

#pragma unroll
        for (int kk = 0; kk < BK; kk += 16) {
            wmma::fragment<wmma::matrix_a, 16, 16, 16, __half, wmma::row_major> a[2];
            wmma::fragment<wmma::matrix_b, 16, 16, 16, __half, wmma::row_major> b[2];
#pragma unroll
            for (int i = 0; i < 2; i++)
                wmma::load_matrix_sync(a[i], As + (wrow * 32 + i * 16) * A_LD + kk, A_LD);
#pragma unroll
            for (int j = 0; j < 2; j++)
                wmma::load_matrix_sync(b[j], Bs + kk * B_LD + wcol * 32 + j * 16, B_LD);
#pragma unroll
            for (int i = 0; i < 2; i++)
#pragma unroll
                for (int j = 0; j < 2; j++)
                    wmma::mma_sync(c[i][j], a[i], b[j], c[i][j]);
        }
        __syncthreads();
    }

    // stage fp32 result in smem, convert to fp16, write out
#pragma unroll
    for (int i = 0; i < 2; i++)
#pragma unroll
        for (int j = 0; j < 2; j++)
            wmma::store_matrix_sync(Cs + (wrow * 32 + i * 16) * C_LD + wcol * 32 + j * 16,
                                    c[i][j], C_LD, wmma::mem_row_major);
    __syncthreads();

    if (tid < BM) {
        int grow = row0 + tid;
        if (grow < M) {
            const float* src = Cs + tid * C_LD;
            __half* dst = C + (size_t)grow * Ncols + col0;
#pragma unroll
            for (int cB = 0; cB < BN; cB += 8) {
                __half2 p0 = __floats2half2_rn(src[cB + 0], src[cB + 1]);
                __half2 p1 = __floats2half2_rn(src[cB + 2], src[cB + 3]);
                __half2 p2 = __floats2half2_rn(src[cB + 4], src[cB + 5]);
                __half2 p3 = __floats2half2_rn(src[cB + 6], src[cB + 7]);
                uint4 o;
                o.x = *(unsigned*)&p0; o.y = *(unsigned*)&p1;
                o.z = *(unsigned*)&p2; o.w = *(unsigned*)&p3;
                *(uint4*)(dst + cB) = o;
            }
        }
    }
}

__global__ __launch_bounds__(256) void k_gemm1(int M) {
    gemm_wmma_body(g_xh, g_w1h, g_h1h, M, HID);
}

__global__ __launch_bounds__(256) void k_gemm2(int M) {
    gemm_wmma_body(g_z1h, g_w2h, g_h2h, M, OUT_CH);
}

// ---------------- CSR aggregation (x4 unrolled, per-src dinv) --------------
// acc = dinv[node]*h[node] + sum_nbr dinv[nb]*h[nb];  out = act(acc*dinv[node]+b)
__device__ __forceinline__ void acc8_add(float* acc, uint4 v, float s) {
    const __half2* p = (const __half2*)&v;
#pragma unroll
    for (int j = 0; j < 4; j++) {
        float2 f = __half22float2(p[j]);
        acc[2 * j]     += s * f.x;
        acc[2 * j + 1] += s * f.y;
    }
}

__global__ __launch_bounds__(256) void k_agg1(const float* __restrict__ bias, int n)
{
    int node = (blockIdx.x * blockDim.x + threadIdx.x) >> 5;
    if (node >= n) return;
    int lane = threadIdx.x & 31;
    float di = g_dinv[node];

    float acc[8] = {0.f, 0.f, 0.f, 0.f, 0.f, 0.f, 0.f, 0.f};
    acc8_add(acc, __ldg((const uint4*)(g_h1h + (size_t)node * HID) + lane), di);

    int beg = g_rowstart[node];
    int end = g_rowstart[node + 1];
    int i = beg;
    for (; i + 4 <= end; i += 4) {
        int nb0 = g_csr[i], nb1 = g_csr[i + 1], nb2 = g_csr[i + 2], nb3 = g_csr[i + 3];
        float s0 = g_dinv[nb0], s1 = g_dinv[nb1], s2 = g_dinv[nb2], s3 = g_dinv[nb3];
        uint4 v0 = __ldg((const uint4*)(g_h1h + (size_t)nb0 * HID) + lane);
        uint4 v1 = __ldg((const uint4*)(g_h1h + (size_t)nb1 * HID) + lane);
        uint4 v2 = __ldg((const uint4*)(g_h1h + (size_t)nb2 * HID) + lane);
        uint4 v3 = __ldg((const uint4*)(g_h1h + (size_t)nb3 * HID) + lane);
        acc8_add(acc, v0, s0);
        acc8_add(acc, v1, s1);
        acc8_add(acc, v2, s2);
        acc8_add(acc, v3, s3);
    }
    for (; i < end; i++) {
        int nb = g_csr[i];
        acc8_add(acc, __ldg((const uint4*)(g_h1h + (size_t)nb * HID) + lane), g_dinv[nb]);
    }

    float4 b0 = __ldg((const float4*)bias + lane * 2);
    float4 b1v = __ldg((const float4*)bias + lane * 2 + 1);
    float o[8];
    o[0] = fmaxf(acc[0] * di + b0.x, 0.f);
    o[1] = fmaxf(acc[1] * di + b0.y, 0.f);
    o[2] = fmaxf(acc[2] * di + b0.z, 0.f);
    o[3] = fmaxf(acc[3] * di + b0.w, 0.f);
    o[4] = fmaxf(acc[4] * di + b1v.x, 0.f);
    o[5] = fmaxf(acc[5] * di + b1v.y, 0.f);
    o[6] = fmaxf(acc[6] * di + b1v.z, 0.f);
    o[7] = fmaxf(acc[7] * di + b1v.w, 0.f);
    __half2 h0 = __floats2half2_rn(o[0], o[1]);
    __half2 h1 = __floats2half2_rn(o[2], o[3]);
    __half2 h2 = __floats2half2_rn(o[4], o[5]);
    __half2 h3 = __floats2half2_rn(o[6], o[7]);
    uint4 ov;
    ov.x = *(unsigned*)&h0; ov.y = *(unsigned*)&h1;
    ov.z = *(unsigned*)&h2; ov.w = *(unsigned*)&h3;
    *((uint4*)(g_z1h + (size_t)node * HID) + lane) = ov;
}

__device__ __forceinline__ void acc4_add(float* acc, uint2 v, float s) {
    const __half2* p = (const __half2*)&v;
    float2 f0 = __half22float2(p[0]);
    float2 f1 = __half22float2(p[1]);
    acc[0] += s * f0.x; acc[1] += s * f0.y;
    acc[2] += s * f1.x; acc[3] += s * f1.y;
}

__global__ __launch_bounds__(256) void k_agg2(const float* __restrict__ bias, int n)
{
    int node = (blockIdx.x * blockDim.x + threadIdx.x) >> 5;
    if (node >= n) return;
    int lane = threadIdx.x & 31;
    float di = g_dinv[node];

    float acc[4] = {0.f, 0.f, 0.f, 0.f};
    acc4_add(acc, __ldg((const uint2*)(g_h2h + (size_t)node * OUT_CH) + lane), di);

    int beg = g_rowstart[node];
    int end = g_rowstart[node + 1];
    int i = beg;
    for (; i + 4 <= end; i += 4) {
        int nb0 = g_csr[i], nb1 = g_csr[i + 1], nb2 = g_csr[i + 2], nb3 = g_csr[i + 3];
        float s0 = g_dinv[nb0], s1 = g_dinv[nb1], s2 = g_dinv[nb2], s3 = g_dinv[nb3];
        uint2 v0 = __ldg((const uint2*)(g_h2h + (size_t)nb0 * OUT_CH) + lane);
        uint2 v1 = __ldg((const uint2*)(g_h2h + (size_t)nb1 * OUT_CH) + lane);
        uint2 v2 = __ldg((const uint2*)(g_h2h + (size_t)nb2 * OUT_CH) + lane);
        uint2 v3 = __ldg((const uint2*)(g_h2h + (size_t)nb3 * OUT_CH) + lane);
        acc4_add(acc, v0, s0);
        acc4_add(acc, v1, s1);
        acc4_add(acc, v2, s2);
        acc4_add(acc, v3, s3);
    }
    for (; i < end; i++) {
        int nb = g_csr[i];
        acc4_add(acc, __ldg((const uint2*)(g_h2h + (size_t)nb * OUT_CH) + lane), g_dinv[nb]);
    }

    float4 bb = __ldg((const float4*)bias + lane);
    __half2 lo = __floats2half2_rn(acc[0] * di + bb.x, acc[1] * di + bb.y);
    __half2 hi = __floats2half2_rn(acc[2] * di + bb.z, acc[3] * di + bb.w);
    uint2 o;
    o.x = *(unsigned*)&lo;
    o.y = *(unsigned*)&hi;
    *((uint2*)(g_z2h + (size_t)node * OUT_CH) + lane) = o;
}

// ---------------- decoder: warp per edge, fp16 rows, fp32 dot --------------
__global__ __launch_bounds__(256) void k_decode(
    const int* __restrict__ ei, float* __restrict__ out, int E, int n)
{
    int warp = (blockIdx.x * blockDim.x + threadIdx.x) >> 5;
    if (warp >= E) return;
    int lane = threadIdx.x & 31;
    int s = __ldg(&ei[warp]);
    int d = __ldg(&ei[(size_t)E + warp]);
    if ((unsigned)s >= (unsigned)n || (unsigned)d >= (unsigned)n) {
        if (lane == 0) out[warp] = 0.f;
        return;
    }
    uint2 va = __ldg((const uint2*)(g_z2h + (size_t)s * OUT_CH) + lane);
    uint2 vb = __ldg((const uint2*)(g_z2h + (size_t)d * OUT_CH) + lane);
    const __half2* pa = (const __half2*)&va;
    const __half2* pb = (const __half2*)&vb;
    float2 a0 = __half22float2(pa[0]), a1 = __half22float2(pa[1]);
    float2 b0 = __half22float2(pb[0]), b1 = __half22float2(pb[1]);
    float p = a0.x * b0.x + a0.y * b0.y + a1.x * b1.x + a1.y * b1.y;
#pragma unroll
    for (int off = 16; off > 0; off >>= 1)
        p += __shfl_down_sync(0xffffffffu, p, off);
    if (lane == 0) out[warp] = p;
}

// ---------------- launch ---------------------------------------------------
extern "C" void kernel_launch(void* const* d_in, const int* in_sizes, int n_in,
                              void* d_out, int out_size)
{
    const float* x  = (const float*)d_in[0];
    const int*   ei = (const int*)d_in[1];   // [2, E] indices, staged as int32
    const float* W1 = (const float*)d_in[2];
    const float* b1 = (const float*)d_in[3];
    const float* W2 = (const float*)d_in[4];
    const float* b2 = (const float*)d_in[5];
    float* out = (float*)d_out;

    int n = in_sizes[0] / IN_CH;    // 50000
    int E = in_sizes[1] / 2;        // 1600000

    // Fork a second stream (capture-legal event fork/join). This code runs only
    // during the single capture call, never during graph replay.
    cudaStream_t s2;
    cudaStreamCreate(&s2);
    cudaEvent_t evFork, evJoin;
    cudaEventCreateWithFlags(&evFork, cudaEventDisableTiming);
    cudaEventCreateWithFlags(&evJoin, cudaEventDisableTiming);

    cudaEventRecord(evFork, 0);
    cudaStreamWaitEvent(s2, evFork, 0);

    // Branch A (default stream): CSR build (atomics / ALU bound)
    k_zero_cnt<<<(n + 255) / 256, 256>>>(n);
    k_count<<<(E + 255) / 256, 256>>>(ei, E, n);
    k_scan<<<1, 1024>>>(n);
    k_fill<<<(E + 255) / 256, 256>>>(ei, E, n);

    // Branch B (s2): fp16 conversions + GEMM1 (tensor / L2 bound, no dinv dep)
    k_cvt_x<<<(n * (IN_CH / 4) + 255) / 256, 256, 0, s2>>>(x, n);
    k_cvt_w1<<<(GK * HID / 4 + 255) / 256, 256, 0, s2>>>(W1);
    k_cvt_w2<<<(GK * OUT_CH / 4 + 255) / 256, 256, 0, s2>>>(W2);
    {
        dim3 grid(HID / BN, (n + BM - 1) / BM);
        k_gemm1<<<grid, 256, 0, s2>>>(n);
    }
    cudaEventRecord(evJoin, s2);
    cudaStreamWaitEvent(0, evJoin, 0);

    // Joined: layer-1 aggregation, layer 2, decode (default stream)
    k_agg1<<<(n * 32 + 255) / 256, 256>>>(b1, n);
    {
        dim3 grid(OUT_CH / BN, (n + BM - 1) / BM);
        k_gemm2<<<grid, 256>>>(n);
    }
    k_agg2<<<(n * 32 + 255) / 256, 256>>>(b2, n);
    k_decode<<<(E * 32 + 255) / 256, 256>>>(ei, out, E, n);

    cudaEventDestroy(evFork);
    cudaEventDestroy(evJoin);
    cudaStreamDestroy(s2);
}

// round 9
// speedup vs baseline: 1.9657x; 1.2542x over previous
#include <cuda_runtime.h>
#include <cuda_fp16.h>
#include <mma.h>
#include <cstdint>

using namespace nvcuda;

// Problem constants (GAE: GCN encoder x2 + inner-product decoder)
#define NN 50000
#define NE 1600000
#define IN_CH 256
#define HID 256
#define OUT_CH 128
#define GK 256   // K dim of both GEMMs

// ---------------- scratch (static device globals; no allocation) ----------
__device__ __align__(256) int    g_cnt[NN];
__device__ __align__(256) int    g_rowstart[NN + 1];
__device__ __align__(256) int    g_pos[NN];
__device__ __align__(256) float  g_dinv[NN];
__device__ __align__(256) int    g_csr[NE];
__device__ __align__(256) __half g_xh[(size_t)NN * IN_CH];    // fp16 x (unscaled)
__device__ __align__(256) __half g_w1h[GK * HID];             // fp16 W1
__device__ __align__(256) __half g_w2h[GK * OUT_CH];          // fp16 W2
__device__ __align__(256) __half g_h1h[(size_t)NN * HID];     // fp16: x@W1, then *= dinv[row]
__device__ __align__(256) __half g_z1h[(size_t)NN * HID];     // fp16: relu(agg*di+b1)*di
__device__ __align__(256) __half g_h2h[(size_t)NN * OUT_CH];  // fp16: z1h@W2 (rows pre-scaled)
__device__ __align__(256) __half g_z2h[(size_t)NN * OUT_CH];  // fp16: agg*di+b2

// ---------------- degree / CSR build --------------------------------------
// edge_index staged as int32, layout [2,E]: src=ei[e], dst=ei[E+e].
__global__ void k_zero_cnt(int n) {
    int i = blockIdx.x * blockDim.x + threadIdx.x;
    if (i < n) g_cnt[i] = 0;
}

__global__ void k_count(const int* __restrict__ ei, int E, int n) {
    int e = blockIdx.x * blockDim.x + threadIdx.x;
    if (e < E) {
        int d = ei[(size_t)E + e];
        if ((unsigned)d < (unsigned)n) atomicAdd(&g_cnt[d], 1);
    }
}

__global__ void k_scan(int n) {
    __shared__ int part[1024];
    int t = threadIdx.x;
    const int CHUNK = (NN + 1023) / 1024;
    int lo = t * CHUNK;
    int hi = lo + CHUNK; if (hi > n) hi = n;
    int s = 0;
    for (int i = lo; i < hi; i++) s += g_cnt[i];
    part[t] = s;
    __syncthreads();
    for (int off = 1; off < 1024; off <<= 1) {
        int v = (t >= off) ? part[t - off] : 0;
        __syncthreads();
        part[t] += v;
        __syncthreads();
    }
    int base = (t == 0) ? 0 : part[t - 1];
    for (int i = lo; i < hi; i++) {
        g_rowstart[i] = base;
        g_pos[i] = base;
        g_dinv[i] = rsqrtf((float)(g_cnt[i] + 1));
        base += g_cnt[i];
    }
    if (t == 0) g_rowstart[n] = part[1023];
}

__global__ void k_fill(const int* __restrict__ ei, int E, int n) {
    int e = blockIdx.x * blockDim.x + threadIdx.x;
    if (e < E) {
        int s = ei[e];
        int d = ei[(size_t)E + e];
        if ((unsigned)s < (unsigned)n && (unsigned)d < (unsigned)n) {
            int p = atomicAdd(&g_pos[d], 1);
            if ((unsigned)p < (unsigned)NE) g_csr[p] = s;
        }
    }
}

// ---------------- conversions (no dinv dependency -> overlappable) --------
__device__ __forceinline__ void cvt_chunk(const float* __restrict__ S,
                                          __half* __restrict__ D, int i) {
    float4 v = __ldg((const float4*)S + i);
    __half2 lo = __floats2half2_rn(v.x, v.y);
    __half2 hi = __floats2half2_rn(v.z, v.w);
    uint2 o; o.x = *(unsigned*)&lo; o.y = *(unsigned*)&hi;
    *((uint2*)D + i) = o;
}

__global__ void k_cvt_x(const float* __restrict__ x, int n) {
    int i = blockIdx.x * blockDim.x + threadIdx.x;
    if (i < n * (IN_CH / 4)) cvt_chunk(x, g_xh, i);
}

// both weight matrices in one launch
__global__ void k_cvt_w(const float* __restrict__ W1, const float* __restrict__ W2) {
    int i = blockIdx.x * blockDim.x + threadIdx.x;
    const int C1 = GK * HID / 4;
    const int C2 = GK * OUT_CH / 4;
    if (i < C1) cvt_chunk(W1, g_w1h, i);
    else if (i < C1 + C2) cvt_chunk(W2, g_w2h, i - C1);
}

// post-join: h1h[row,:] *= dinv[row]   (streaming, ~6us)
__global__ void k_scale_h1(int n) {
    int i = blockIdx.x * blockDim.x + threadIdx.x;   // one uint4 (8 halves)
    int total = n * (HID / 8);
    if (i >= total) return;
    float di = g_dinv[i / (HID / 8)];
    uint4 v = *((const uint4*)g_h1h + i);
    __half2* p = (__half2*)&v;
#pragma unroll
    for (int j = 0; j < 4; j++) {
        float2 f = __half22float2(p[j]);
        p[j] = __floats2half2_rn(f.x * di, f.y * di);
    }
    *((uint4*)g_h1h + i) = v;
}

// ---------------- wmma fp16 GEMM: C = A[M,256] @ B[256,Ncols] --------------
// BM=128, BN=64, BK=32; 256 threads = 8 warps in 4x2; each warp 32x32 (2x2 frags).
#define BM 128
#define BN 64
#define BK 32
#define A_LD 40   // BK + 8 pad (halves)
#define B_LD 72   // BN + 8 pad (halves)
#define C_LD 68   // BN + 4 pad (floats)

__device__ __forceinline__ void gemm_wmma_body(
    const __half* __restrict__ A, const __half* __restrict__ B,
    __half* __restrict__ C, int M, int Ncols)
{
    __shared__ __align__(16) char sm[BM * C_LD * 4];   // 34816 B; unioned A/B vs C
    __half* As = (__half*)sm;                          // [BM][A_LD]
    __half* Bs = As + BM * A_LD;                       // [BK][B_LD]
    float*  Cs = (float*)sm;                           // [BM][C_LD]

    int tid = threadIdx.x;
    int warp = tid >> 5;
    int wrow = warp >> 1;          // 0..3  -> 32-row band
    int wcol = warp & 1;           // 0..1  -> 32-col band
    int row0 = blockIdx.y * BM;
    int col0 = blockIdx.x * BN;

    wmma::fragment<wmma::accumulator, 16, 16, 16, float> c[2][2];
#pragma unroll
    for (int i = 0; i < 2; i++)
#pragma unroll
        for (int j = 0; j < 2; j++) wmma::fill_fragment(c[i][j], 0.f);

    for (int k0 = 0; k0 < GK; k0 += BK) {
        // load A tile: BM x BK halves, 2 uint4 per thread
#pragma unroll
        for (int t = 0; t < 2; t++) {
            int v = tid + t * 256;          // 0..511
            int r = v >> 2;                 // 0..127
            int kc = (v & 3) * 8;           // 0,8,16,24
            int grow = row0 + r;
            uint4 val = make_uint4(0u, 0u, 0u, 0u);
            if (grow < M)
                val = *(const uint4*)(A + (size_t)grow * GK + k0 + kc);
            *(uint4*)(As + r * A_LD + kc) = val;
        }
        // load B tile: BK x BN halves, 1 uint4 per thread
        {
            int r = tid >> 3;               // 0..31
            int c8 = (tid & 7) * 8;         // 0..56
            uint4 val = *(const uint4*)(B + (size_t)(k0 + r) * Ncols + col0 + c8);
            *(uint4*)(Bs + r * B_LD + c8) = val;
        }
        __syncthreads();

#pragma unroll
        for (int kk = 0; kk < BK; kk += 16) {
            wmma::fragment<wmma::matrix_a, 16, 16, 16, __half, wmma::row_major> a[2];
            wmma::fragment<wmma::matrix_b, 16, 16, 16, __half, wmma::row_major> b[2];
#pragma unroll
            for (int i = 0; i < 2; i++)
                wmma::load_matrix_sync(a[i], As + (wrow * 32 + i * 16) * A_LD + kk, A_LD);
#pragma unroll
            for (int j = 0; j < 2; j++)
                wmma::load_matrix_sync(b[j], Bs + kk * B_LD + wcol * 32 + j * 16, B_LD);
#pragma unroll
            for (int i = 0; i < 2; i++)
#pragma unroll
                for (int j = 0; j < 2; j++)
                    wmma::mma_sync(c[i][j], a[i], b[j], c[i][j]);
        }
        __syncthreads();
    }

    // stage fp32 result in smem, convert to fp16, write out
#pragma unroll
    for (int i = 0; i < 2; i++)
#pragma unroll
        for (int j = 0; j < 2; j++)
            wmma::store_matrix_sync(Cs + (wrow * 32 + i * 16) * C_LD + wcol * 32 + j * 16,
                                    c[i][j], C_LD, wmma::mem_row_major);
    __syncthreads();

    if (tid < BM) {
        int grow = row0 + tid;
        if (grow < M) {
            const float* src = Cs + tid * C_LD;
            __half* dst = C + (size_t)grow * Ncols + col0;
#pragma unroll
            for (int cB = 0; cB < BN; cB += 8) {
                __half2 p0 = __floats2half2_rn(src[cB + 0], src[cB + 1]);
                __half2 p1 = __floats2half2_rn(src[cB + 2], src[cB + 3]);
                __half2 p2 = __floats2half2_rn(src[cB + 4], src[cB + 5]);
                __half2 p3 = __floats2half2_rn(src[cB + 6], src[cB + 7]);
                uint4 o;
                o.x = *(unsigned*)&p0; o.y = *(unsigned*)&p1;
                o.z = *(unsigned*)&p2; o.w = *(unsigned*)&p3;
                *(uint4*)(dst + cB) = o;
            }
        }
    }
}

__global__ __launch_bounds__(256) void k_gemm1(int M) {
    gemm_wmma_body(g_xh, g_w1h, g_h1h, M, HID);
}

__global__ __launch_bounds__(256) void k_gemm2(int M) {
    gemm_wmma_body(g_z1h, g_w2h, g_h2h, M, OUT_CH);
}

// ---------------- CSR aggregation (pure row-sum; rows pre-scaled) ----------
__device__ __forceinline__ void acc8_add(float* acc, uint4 v) {
    const __half2* p = (const __half2*)&v;
#pragma unroll
    for (int j = 0; j < 4; j++) {
        float2 f = __half22float2(p[j]);
        acc[2 * j]     += f.x;
        acc[2 * j + 1] += f.y;
    }
}

// agg1: acc = sum of pre-scaled h1h rows (self + nbrs);
//       z1h = relu(acc*di + b1) * di   (carry dinv into layer 2)
__global__ __launch_bounds__(256) void k_agg1(const float* __restrict__ bias, int n)
{
    int node = (blockIdx.x * blockDim.x + threadIdx.x) >> 5;
    if (node >= n) return;
    int lane = threadIdx.x & 31;

    float acc[8] = {0.f, 0.f, 0.f, 0.f, 0.f, 0.f, 0.f, 0.f};
    acc8_add(acc, __ldg((const uint4*)(g_h1h + (size_t)node * HID) + lane));

    int beg = g_rowstart[node];
    int end = g_rowstart[node + 1];
    int i = beg;
    for (; i + 4 <= end; i += 4) {
        int nb0 = g_csr[i], nb1 = g_csr[i + 1], nb2 = g_csr[i + 2], nb3 = g_csr[i + 3];
        uint4 v0 = __ldg((const uint4*)(g_h1h + (size_t)nb0 * HID) + lane);
        uint4 v1 = __ldg((const uint4*)(g_h1h + (size_t)nb1 * HID) + lane);
        uint4 v2 = __ldg((const uint4*)(g_h1h + (size_t)nb2 * HID) + lane);
        uint4 v3 = __ldg((const uint4*)(g_h1h + (size_t)nb3 * HID) + lane);
        acc8_add(acc, v0);
        acc8_add(acc, v1);
        acc8_add(acc, v2);
        acc8_add(acc, v3);
    }
    for (; i < end; i++) {
        int nb = g_csr[i];
        acc8_add(acc, __ldg((const uint4*)(g_h1h + (size_t)nb * HID) + lane));
    }

    float di = g_dinv[node];
    float4 b0 = __ldg((const float4*)bias + lane * 2);
    float4 b1v = __ldg((const float4*)bias + lane * 2 + 1);
    float o[8];
    o[0] = fmaxf(acc[0] * di + b0.x, 0.f) * di;
    o[1] = fmaxf(acc[1] * di + b0.y, 0.f) * di;
    o[2] = fmaxf(acc[2] * di + b0.z, 0.f) * di;
    o[3] = fmaxf(acc[3] * di + b0.w, 0.f) * di;
    o[4] = fmaxf(acc[4] * di + b1v.x, 0.f) * di;
    o[5] = fmaxf(acc[5] * di + b1v.y, 0.f) * di;
    o[6] = fmaxf(acc[6] * di + b1v.z, 0.f) * di;
    o[7] = fmaxf(acc[7] * di + b1v.w, 0.f) * di;
    __half2 h0 = __floats2half2_rn(o[0], o[1]);
    __half2 h1 = __floats2half2_rn(o[2], o[3]);
    __half2 h2 = __floats2half2_rn(o[4], o[5]);
    __half2 h3 = __floats2half2_rn(o[6], o[7]);
    uint4 ov;
    ov.x = *(unsigned*)&h0; ov.y = *(unsigned*)&h1;
    ov.z = *(unsigned*)&h2; ov.w = *(unsigned*)&h3;
    *((uint4*)(g_z1h + (size_t)node * HID) + lane) = ov;
}

__device__ __forceinline__ void acc4_add(float* acc, uint2 v) {
    const __half2* p = (const __half2*)&v;
    float2 f0 = __half22float2(p[0]);
    float2 f1 = __half22float2(p[1]);
    acc[0] += f0.x; acc[1] += f0.y;
    acc[2] += f1.x; acc[3] += f1.y;
}

// agg2: h2h rows already carry dinv[src] (via z1h*di); z2h = acc*di + b2
__global__ __launch_bounds__(256) void k_agg2(const float* __restrict__ bias, int n)
{
    int node = (blockIdx.x * blockDim.x + threadIdx.x) >> 5;
    if (node >= n) return;
    int lane = threadIdx.x & 31;

    float acc[4] = {0.f, 0.f, 0.f, 0.f};
    acc4_add(acc, __ldg((const uint2*)(g_h2h + (size_t)node * OUT_CH) + lane));

    int beg = g_rowstart[node];
    int end = g_rowstart[node + 1];
    int i = beg;
    for (; i + 4 <= end; i += 4) {
        int nb0 = g_csr[i], nb1 = g_csr[i + 1], nb2 = g_csr[i + 2], nb3 = g_csr[i + 3];
        uint2 v0 = __ldg((const uint2*)(g_h2h + (size_t)nb0 * OUT_CH) + lane);
        uint2 v1 = __ldg((const uint2*)(g_h2h + (size_t)nb1 * OUT_CH) + lane);
        uint2 v2 = __ldg((const uint2*)(g_h2h + (size_t)nb2 * OUT_CH) + lane);
        uint2 v3 = __ldg((const uint2*)(g_h2h + (size_t)nb3 * OUT_CH) + lane);
        acc4_add(acc, v0);
        acc4_add(acc, v1);
        acc4_add(acc, v2);
        acc4_add(acc, v3);
    }
    for (; i < end; i++) {
        int nb = g_csr[i];
        acc4_add(acc, __ldg((const uint2*)(g_h2h + (size_t)nb * OUT_CH) + lane));
    }

    float di = g_dinv[node];
    float4 bb = __ldg((const float4*)bias + lane);
    __half2 lo = __floats2half2_rn(acc[0] * di + bb.x, acc[1] * di + bb.y);
    __half2 hi = __floats2half2_rn(acc[2] * di + bb.z, acc[3] * di + bb.w);
    uint2 o;
    o.x = *(unsigned*)&lo;
    o.y = *(unsigned*)&hi;
    *((uint2*)(g_z2h + (size_t)node * OUT_CH) + lane) = o;
}

// ---------------- decoder: 2 edges per warp, 16 lanes each, uint4 loads ----
__global__ __launch_bounds__(256) void k_decode(
    const int* __restrict__ ei, float* __restrict__ out, int E, int n)
{
    int warp = (blockIdx.x * blockDim.x + threadIdx.x) >> 5;
    int lane = threadIdx.x & 31;
    int half = lane >> 4;          // 0 or 1
    int l16  = lane & 15;
    int e = warp * 2 + half;
    if (e >= E) return;

    int s = __ldg(&ei[e]);
    int d = __ldg(&ei[(size_t)E + e]);
    float p = 0.f;
    if ((unsigned)s < (unsigned)n && (unsigned)d < (unsigned)n) {
        uint4 va = __ldg((const uint4*)(g_z2h + (size_t)s * OUT_CH) + l16);
        uint4 vb = __ldg((const uint4*)(g_z2h + (size_t)d * OUT_CH) + l16);
        const __half2* pa = (const __half2*)&va;
        const __half2* pb = (const __half2*)&vb;
#pragma unroll
        for (int j = 0; j < 4; j++) {
            float2 a = __half22float2(pa[j]);
            float2 b = __half22float2(pb[j]);
            p += a.x * b.x + a.y * b.y;
        }
    }
#pragma unroll
    for (int off = 8; off > 0; off >>= 1)
        p += __shfl_down_sync(0xffffffffu, p, off, 16);
    if (l16 == 0) out[e] = p;
}

// ---------------- launch ---------------------------------------------------
extern "C" void kernel_launch(void* const* d_in, const int* in_sizes, int n_in,
                              void* d_out, int out_size)
{
    const float* x  = (const float*)d_in[0];
    const int*   ei = (const int*)d_in[1];   // [2, E] indices, staged as int32
    const float* W1 = (const float*)d_in[2];
    const float* b1 = (const float*)d_in[3];
    const float* W2 = (const float*)d_in[4];
    const float* b2 = (const float*)d_in[5];
    float* out = (float*)d_out;

    int n = in_sizes[0] / IN_CH;    // 50000
    int E = in_sizes[1] / 2;        // 1600000

    // Fork a second stream (capture-legal event fork/join; runs only at capture).
    cudaStream_t s2;
    cudaStreamCreate(&s2);
    cudaEvent_t evFork, evJoin;
    cudaEventCreateWithFlags(&evFork, cudaEventDisableTiming);
    cudaEventCreateWithFlags(&evJoin, cudaEventDisableTiming);

    cudaEventRecord(evFork, 0);
    cudaStreamWaitEvent(s2, evFork, 0);

    // Branch A (default stream): CSR build (atomics / ALU bound)
    k_zero_cnt<<<(n + 255) / 256, 256>>>(n);
    k_count<<<(E + 255) / 256, 256>>>(ei, E, n);
    k_scan<<<1, 1024>>>(n);
    k_fill<<<(E + 255) / 256, 256>>>(ei, E, n);

    // Branch B (s2): fp16 conversions + GEMM1 (tensor / L2 bound, no dinv dep)
    k_cvt_x<<<(n * (IN_CH / 4) + 255) / 256, 256, 0, s2>>>(x, n);
    k_cvt_w<<<((GK * HID + GK * OUT_CH) / 4 + 255) / 256, 256, 0, s2>>>(W1, W2);
    {
        dim3 grid(HID / BN, (n + BM - 1) / BM);
        k_gemm1<<<grid, 256, 0, s2>>>(n);
    }
    cudaEventRecord(evJoin, s2);
    cudaStreamWaitEvent(0, evJoin, 0);

    // Joined (default stream): scale h1 rows, layer-1 agg, layer 2, decode
    k_scale_h1<<<(n * (HID / 8) + 255) / 256, 256>>>(n);
    k_agg1<<<(n * 32 + 255) / 256, 256>>>(b1, n);
    {
        dim3 grid(OUT_CH / BN, (n + BM - 1) / BM);
        k_gemm2<<<grid, 256>>>(n);
    }
    k_agg2<<<(n * 32 + 255) / 256, 256>>>(b2, n);
    k_decode<<<((E / 2 + 1) * 32 + 255) / 256, 256>>>(ei, out, E, n);

    cudaEventDestroy(evFork);
    cudaEventDestroy(evJoin);
    cudaStreamDestroy(s2);
}

// round 10
// speedup vs baseline: 2.1639x; 1.1008x over previous
#include <cuda_runtime.h>
#include <cuda_fp16.h>
#include <mma.h>
#include <cstdint>

using namespace nvcuda;

// Problem constants (GAE: GCN encoder x2 + inner-product decoder)
#define NN 50000
#define NE 1600000
#define IN_CH 256
#define HID 256
#define OUT_CH 128
#define GK 256   // K dim of both GEMMs

// ---------------- scratch (static device globals; no allocation) ----------
__device__ __align__(256) int    g_cnt[NN];
__device__ __align__(256) int    g_rowstart[NN + 1];
__device__ __align__(256) int    g_pos[NN];
__device__ __align__(256) float  g_dinv[NN];
__device__ __align__(256) int    g_csr[NE];
__device__ __align__(256) __half g_xh[(size_t)NN * IN_CH];    // fp16 x (unscaled)
__device__ __align__(256) __half g_w1h[GK * HID];             // fp16 W1
__device__ __align__(256) __half g_w2h[GK * OUT_CH];          // fp16 W2
__device__ __align__(256) __half g_h1h[(size_t)NN * HID];     // fp16: x@W1, then *= dinv[row]
__device__ __align__(256) __half g_z1h[(size_t)NN * HID];     // fp16: relu(agg*di+b1)*di
__device__ __align__(256) __half g_h2h[(size_t)NN * OUT_CH];  // fp16: z1h@W2 (rows pre-scaled)
__device__ __align__(256) __half g_z2h[(size_t)NN * OUT_CH];  // fp16: agg*di+b2

// ---------------- degree / CSR build --------------------------------------
__global__ void k_zero_cnt(int n) {
    int i = blockIdx.x * blockDim.x + threadIdx.x;
    if (i < n) g_cnt[i] = 0;
}

__global__ void k_count(const int* __restrict__ ei, int E, int n) {
    int e = blockIdx.x * blockDim.x + threadIdx.x;
    if (e < E) {
        int d = ei[(size_t)E + e];
        if ((unsigned)d < (unsigned)n) atomicAdd(&g_cnt[d], 1);
    }
}

__global__ void k_scan(int n) {
    __shared__ int part[1024];
    int t = threadIdx.x;
    const int CHUNK = (NN + 1023) / 1024;
    int lo = t * CHUNK;
    int hi = lo + CHUNK; if (hi > n) hi = n;
    int s = 0;
    for (int i = lo; i < hi; i++) s += g_cnt[i];
    part[t] = s;
    __syncthreads();
    for (int off = 1; off < 1024; off <<= 1) {
        int v = (t >= off) ? part[t - off] : 0;
        __syncthreads();
        part[t] += v;
        __syncthreads();
    }
    int base = (t == 0) ? 0 : part[t - 1];
    for (int i = lo; i < hi; i++) {
        g_rowstart[i] = base;
        g_pos[i] = base;
        g_dinv[i] = rsqrtf((float)(g_cnt[i] + 1));
        base += g_cnt[i];
    }
    if (t == 0) g_rowstart[n] = part[1023];
}

__global__ void k_fill(const int* __restrict__ ei, int E, int n) {
    int e = blockIdx.x * blockDim.x + threadIdx.x;
    if (e < E) {
        int s = ei[e];
        int d = ei[(size_t)E + e];
        if ((unsigned)s < (unsigned)n && (unsigned)d < (unsigned)n) {
            int p = atomicAdd(&g_pos[d], 1);
            if ((unsigned)p < (unsigned)NE) g_csr[p] = s;
        }
    }
}

// ---------------- conversions (no dinv dependency -> overlappable) --------
__device__ __forceinline__ void cvt_chunk(const float* __restrict__ S,
                                          __half* __restrict__ D, int i) {
    float4 v = __ldg((const float4*)S + i);
    __half2 lo = __floats2half2_rn(v.x, v.y);
    __half2 hi = __floats2half2_rn(v.z, v.w);
    uint2 o; o.x = *(unsigned*)&lo; o.y = *(unsigned*)&hi;
    *((uint2*)D + i) = o;
}

__global__ void k_cvt_x(const float* __restrict__ x, int n) {
    int i = blockIdx.x * blockDim.x + threadIdx.x;
    if (i < n * (IN_CH / 4)) cvt_chunk(x, g_xh, i);
}

__global__ void k_cvt_w(const float* __restrict__ W1, const float* __restrict__ W2) {
    int i = blockIdx.x * blockDim.x + threadIdx.x;
    const int C1 = GK * HID / 4;
    const int C2 = GK * OUT_CH / 4;
    if (i < C1) cvt_chunk(W1, g_w1h, i);
    else if (i < C1 + C2) cvt_chunk(W2, g_w2h, i - C1);
}

// post-join: h1h[row,:] *= dinv[row]
__global__ void k_scale_h1(int n) {
    int i = blockIdx.x * blockDim.x + threadIdx.x;   // one uint4 (8 halves)
    int total = n * (HID / 8);
    if (i >= total) return;
    float di = g_dinv[i / (HID / 8)];
    uint4 v = *((const uint4*)g_h1h + i);
    __half2* p = (__half2*)&v;
#pragma unroll
    for (int j = 0; j < 4; j++) {
        float2 f = __half22float2(p[j]);
        p[j] = __floats2half2_rn(f.x * di, f.y * di);
    }
    *((uint4*)g_h1h + i) = v;
}

// ---------------- wmma fp16 GEMM: C = A[M,256] @ B[256,Ncols] --------------
#define BM 128
#define BN 64
#define BK 32
#define A_LD 40   // BK + 8 pad (halves)
#define B_LD 72   // BN + 8 pad (halves)
#define C_LD 68   // BN + 4 pad (floats)

__device__ __forceinline__ void gemm_wmma_body(
    const __half* __restrict__ A, const __half* __restrict__ B,
    __half* __restrict__ C, int rowBase, int M, int Ncols)
{
    __shared__ __align__(16) char sm[BM * C_LD * 4];   // 34816 B; unioned A/B vs C
    __half* As = (__half*)sm;                          // [BM][A_LD]
    __half* Bs = As + BM * A_LD;                       // [BK][B_LD]
    float*  Cs = (float*)sm;                           // [BM][C_LD]

    int tid = threadIdx.x;
    int warp = tid >> 5;
    int wrow = warp >> 1;
    int wcol = warp & 1;
    int row0 = rowBase + blockIdx.y * BM;
    int col0 = blockIdx.x * BN;

    wmma::fragment<wmma::accumulator, 16, 16, 16, float> c[2][2];
#pragma unroll
    for (int i = 0; i < 2; i++)
#pragma unroll
        for (int j = 0; j < 2; j++) wmma::fill_fragment(c[i][j], 0.f);

    for (int k0 = 0; k0 < GK; k0 += BK) {
#pragma unroll
        for (int t = 0; t < 2; t++) {
            int v = tid + t * 256;
            int r = v >> 2;
            int kc = (v & 3) * 8;
            int grow = row0 + r;
            uint4 val = make_uint4(0u, 0u, 0u, 0u);
            if (grow < M)
                val = *(const uint4*)(A + (size_t)grow * GK + k0 + kc);
            *(uint4*)(As + r * A_LD + kc) = val;
        }
        {
            int r = tid >> 3;
            int c8 = (tid & 7) * 8;
            uint4 val = *(const uint4*)(B + (size_t)(k0 + r) * Ncols + col0 + c8);
            *(uint4*)(Bs + r * B_LD + c8) = val;
        }
        __syncthreads();

#pragma unroll
        for (int kk = 0; kk < BK; kk += 16) {
            wmma::fragment<wmma::matrix_a, 16, 16, 16, __half, wmma::row_major> a[2];
            wmma::fragment<wmma::matrix_b, 16, 16, 16, __half, wmma::row_major> b[2];
#pragma unroll
            for (int i = 0; i < 2; i++)
                wmma::load_matrix_sync(a[i], As + (wrow * 32 + i * 16) * A_LD + kk, A_LD);
#pragma unroll
            for (int j = 0; j < 2; j++)
                wmma::load_matrix_sync(b[j], Bs + kk * B_LD + wcol * 32 + j * 16, B_LD);
#pragma unroll
            for (int i = 0; i < 2; i++)
#pragma unroll
                for (int j = 0; j < 2; j++)
                    wmma::mma_sync(c[i][j], a[i], b[j], c[i][j]);
        }
        __syncthreads();
    }

#pragma unroll
    for (int i = 0; i < 2; i++)
#pragma unroll
        for (int j = 0; j < 2; j++)
            wmma::store_matrix_sync(Cs + (wrow * 32 + i * 16) * C_LD + wcol * 32 + j * 16,
                                    c[i][j], C_LD, wmma::mem_row_major);
    __syncthreads();

    if (tid < BM) {
        int grow = row0 + tid;
        if (grow < M) {
            const float* src = Cs + tid * C_LD;
            __half* dst = C + (size_t)grow * Ncols + col0;
#pragma unroll
            for (int cB = 0; cB < BN; cB += 8) {
                __half2 p0 = __floats2half2_rn(src[cB + 0], src[cB + 1]);
                __half2 p1 = __floats2half2_rn(src[cB + 2], src[cB + 3]);
                __half2 p2 = __floats2half2_rn(src[cB + 4], src[cB + 5]);
                __half2 p3 = __floats2half2_rn(src[cB + 6], src[cB + 7]);
                uint4 o;
                o.x = *(unsigned*)&p0; o.y = *(unsigned*)&p1;
                o.z = *(unsigned*)&p2; o.w = *(unsigned*)&p3;
                *(uint4*)(dst + cB) = o;
            }
        }
    }
}

__global__ __launch_bounds__(256) void k_gemm1(int M) {
    gemm_wmma_body(g_xh, g_w1h, g_h1h, 0, M, HID);
}

__global__ __launch_bounds__(256) void k_gemm2(int rowBase, int M) {
    gemm_wmma_body(g_z1h, g_w2h, g_h2h, rowBase, M, OUT_CH);
}

// ---------------- CSR aggregation (pure row-sum; rows pre-scaled) ----------
__device__ __forceinline__ void acc8_add(float* acc, uint4 v) {
    const __half2* p = (const __half2*)&v;
#pragma unroll
    for (int j = 0; j < 4; j++) {
        float2 f = __half22float2(p[j]);
        acc[2 * j]     += f.x;
        acc[2 * j + 1] += f.y;
    }
}

// agg1 over node range [base, limit): one warp/node, 32 lanes x uint4 = 512B row
__global__ __launch_bounds__(256) void k_agg1(const float* __restrict__ bias,
                                              int base, int limit)
{
    int node = base + ((blockIdx.x * blockDim.x + threadIdx.x) >> 5);
    if (node >= limit) return;
    int lane = threadIdx.x & 31;

    float acc[8] = {0.f, 0.f, 0.f, 0.f, 0.f, 0.f, 0.f, 0.f};
    acc8_add(acc, __ldg((const uint4*)(g_h1h + (size_t)node * HID) + lane));

    int beg = g_rowstart[node];
    int end = g_rowstart[node + 1];
    int i = beg;
    for (; i + 4 <= end; i += 4) {
        int nb0 = g_csr[i], nb1 = g_csr[i + 1], nb2 = g_csr[i + 2], nb3 = g_csr[i + 3];
        uint4 v0 = __ldg((const uint4*)(g_h1h + (size_t)nb0 * HID) + lane);
        uint4 v1 = __ldg((const uint4*)(g_h1h + (size_t)nb1 * HID) + lane);
        uint4 v2 = __ldg((const uint4*)(g_h1h + (size_t)nb2 * HID) + lane);
        uint4 v3 = __ldg((const uint4*)(g_h1h + (size_t)nb3 * HID) + lane);
        acc8_add(acc, v0);
        acc8_add(acc, v1);
        acc8_add(acc, v2);
        acc8_add(acc, v3);
    }
    for (; i < end; i++) {
        int nb = g_csr[i];
        acc8_add(acc, __ldg((const uint4*)(g_h1h + (size_t)nb * HID) + lane));
    }

    float di = g_dinv[node];
    float4 b0 = __ldg((const float4*)bias + lane * 2);
    float4 b1v = __ldg((const float4*)bias + lane * 2 + 1);
    float o[8];
    o[0] = fmaxf(acc[0] * di + b0.x, 0.f) * di;
    o[1] = fmaxf(acc[1] * di + b0.y, 0.f) * di;
    o[2] = fmaxf(acc[2] * di + b0.z, 0.f) * di;
    o[3] = fmaxf(acc[3] * di + b0.w, 0.f) * di;
    o[4] = fmaxf(acc[4] * di + b1v.x, 0.f) * di;
    o[5] = fmaxf(acc[5] * di + b1v.y, 0.f) * di;
    o[6] = fmaxf(acc[6] * di + b1v.z, 0.f) * di;
    o[7] = fmaxf(acc[7] * di + b1v.w, 0.f) * di;
    __half2 h0 = __floats2half2_rn(o[0], o[1]);
    __half2 h1 = __floats2half2_rn(o[2], o[3]);
    __half2 h2 = __floats2half2_rn(o[4], o[5]);
    __half2 h3 = __floats2half2_rn(o[6], o[7]);
    uint4 ov;
    ov.x = *(unsigned*)&h0; ov.y = *(unsigned*)&h1;
    ov.z = *(unsigned*)&h2; ov.w = *(unsigned*)&h3;
    *((uint4*)(g_z1h + (size_t)node * HID) + lane) = ov;
}

// agg2: one node per 16-lane group (row = 128 halves = 16 x uint4)
__global__ __launch_bounds__(256) void k_agg2(const float* __restrict__ bias, int n)
{
    int node = (blockIdx.x * blockDim.x + threadIdx.x) >> 4;
    if (node >= n) return;
    int l16 = threadIdx.x & 15;

    float acc[8] = {0.f, 0.f, 0.f, 0.f, 0.f, 0.f, 0.f, 0.f};
    acc8_add(acc, __ldg((const uint4*)(g_h2h + (size_t)node * OUT_CH) + l16));

    int beg = g_rowstart[node];
    int end = g_rowstart[node + 1];
    int i = beg;
    for (; i + 4 <= end; i += 4) {
        int nb0 = g_csr[i], nb1 = g_csr[i + 1], nb2 = g_csr[i + 2], nb3 = g_csr[i + 3];
        uint4 v0 = __ldg((const uint4*)(g_h2h + (size_t)nb0 * OUT_CH) + l16);
        uint4 v1 = __ldg((const uint4*)(g_h2h + (size_t)nb1 * OUT_CH) + l16);
        uint4 v2 = __ldg((const uint4*)(g_h2h + (size_t)nb2 * OUT_CH) + l16);
        uint4 v3 = __ldg((const uint4*)(g_h2h + (size_t)nb3 * OUT_CH) + l16);
        acc8_add(acc, v0);
        acc8_add(acc, v1);
        acc8_add(acc, v2);
        acc8_add(acc, v3);
    }
    for (; i < end; i++) {
        int nb = g_csr[i];
        acc8_add(acc, __ldg((const uint4*)(g_h2h + (size_t)nb * OUT_CH) + l16));
    }

    float di = g_dinv[node];
    float4 b0 = __ldg((const float4*)bias + l16 * 2);
    float4 b1v = __ldg((const float4*)bias + l16 * 2 + 1);
    __half2 h0 = __floats2half2_rn(acc[0] * di + b0.x,  acc[1] * di + b0.y);
    __half2 h1 = __floats2half2_rn(acc[2] * di + b0.z,  acc[3] * di + b0.w);
    __half2 h2 = __floats2half2_rn(acc[4] * di + b1v.x, acc[5] * di + b1v.y);
    __half2 h3 = __floats2half2_rn(acc[6] * di + b1v.z, acc[7] * di + b1v.w);
    uint4 ov;
    ov.x = *(unsigned*)&h0; ov.y = *(unsigned*)&h1;
    ov.z = *(unsigned*)&h2; ov.w = *(unsigned*)&h3;
    *((uint4*)(g_z2h + (size_t)node * OUT_CH) + l16) = ov;
}

// ---------------- decoder: 4 edges per warp (two 16-lane groups x 2 edges) --
__global__ __launch_bounds__(256) void k_decode(
    const int* __restrict__ ei, float* __restrict__ out, int E, int n)
{
    int warp = (blockIdx.x * blockDim.x + threadIdx.x) >> 5;
    int lane = threadIdx.x & 31;
    int grp  = lane >> 4;          // 0 or 1
    int l16  = lane & 15;
    int e0 = warp * 4 + grp * 2;   // this group's two edges
    int e1 = e0 + 1;
    if (e0 >= E) return;

    int s0 = __ldg(&ei[e0]);
    int d0 = __ldg(&ei[(size_t)E + e0]);
    bool ok0 = (unsigned)s0 < (unsigned)n && (unsigned)d0 < (unsigned)n;
    bool has1 = (e1 < E);
    int s1 = has1 ? __ldg(&ei[e1]) : 0;
    int d1 = has1 ? __ldg(&ei[(size_t)E + e1]) : 0;
    bool ok1 = has1 && (unsigned)s1 < (unsigned)n && (unsigned)d1 < (unsigned)n;

    uint4 va0 = make_uint4(0, 0, 0, 0), vb0 = va0, va1 = va0, vb1 = va0;
    if (ok0) {
        va0 = __ldg((const uint4*)(g_z2h + (size_t)s0 * OUT_CH) + l16);
        vb0 = __ldg((const uint4*)(g_z2h + (size_t)d0 * OUT_CH) + l16);
    }
    if (ok1) {
        va1 = __ldg((const uint4*)(g_z2h + (size_t)s1 * OUT_CH) + l16);
        vb1 = __ldg((const uint4*)(g_z2h + (size_t)d1 * OUT_CH) + l16);
    }

    float p0 = 0.f, p1 = 0.f;
    {
        const __half2* pa = (const __half2*)&va0;
        const __half2* pb = (const __half2*)&vb0;
#pragma unroll
        for (int j = 0; j < 4; j++) {
            float2 a = __half22float2(pa[j]);
            float2 b = __half22float2(pb[j]);
            p0 += a.x * b.x + a.y * b.y;
        }
    }
    {
        const __half2* pa = (const __half2*)&va1;
        const __half2* pb = (const __half2*)&vb1;
#pragma unroll
        for (int j = 0; j < 4; j++) {
            float2 a = __half22float2(pa[j]);
            float2 b = __half22float2(pb[j]);
            p1 += a.x * b.x + a.y * b.y;
        }
    }
#pragma unroll
    for (int off = 8; off > 0; off >>= 1) {
        p0 += __shfl_down_sync(0xffffffffu, p0, off, 16);
        p1 += __shfl_down_sync(0xffffffffu, p1, off, 16);
    }
    if (l16 == 0) {
        out[e0] = p0;
        if (has1) out[e1] = p1;
    }
}

// ---------------- launch ---------------------------------------------------
extern "C" void kernel_launch(void* const* d_in, const int* in_sizes, int n_in,
                              void* d_out, int out_size)
{
    const float* x  = (const float*)d_in[0];
    const int*   ei = (const int*)d_in[1];   // [2, E] indices, staged as int32
    const float* W1 = (const float*)d_in[2];
    const float* b1 = (const float*)d_in[3];
    const float* W2 = (const float*)d_in[4];
    const float* b2 = (const float*)d_in[5];
    float* out = (float*)d_out;

    int n = in_sizes[0] / IN_CH;    // 50000
    int E = in_sizes[1] / 2;        // 1600000
    int nh = ((n / 2 + BM - 1) / BM) * BM;   // chunk split, BM-aligned (25088)
    if (nh > n) nh = n;

    // Streams/events: capture-legal fork/join; runs only at capture time.
    cudaStream_t s2;
    cudaStreamCreate(&s2);
    cudaEvent_t evFork, evJoin, evA, evG2a;
    cudaEventCreateWithFlags(&evFork, cudaEventDisableTiming);
    cudaEventCreateWithFlags(&evJoin, cudaEventDisableTiming);
    cudaEventCreateWithFlags(&evA, cudaEventDisableTiming);
    cudaEventCreateWithFlags(&evG2a, cudaEventDisableTiming);

    cudaEventRecord(evFork, 0);
    cudaStreamWaitEvent(s2, evFork, 0);

    // Branch A (default stream): CSR build (atomics / ALU bound)
    k_zero_cnt<<<(n + 255) / 256, 256>>>(n);
    k_count<<<(E + 255) / 256, 256>>>(ei, E, n);
    k_scan<<<1, 1024>>>(n);
    k_fill<<<(E + 255) / 256, 256>>>(ei, E, n);

    // Branch B (s2): fp16 conversions + GEMM1 (tensor / L2 bound)
    k_cvt_x<<<(n * (IN_CH / 4) + 255) / 256, 256, 0, s2>>>(x, n);
    k_cvt_w<<<((GK * HID + GK * OUT_CH) / 4 + 255) / 256, 256, 0, s2>>>(W1, W2);
    {
        dim3 grid(HID / BN, (n + BM - 1) / BM);
        k_gemm1<<<grid, 256, 0, s2>>>(n);
    }
    cudaEventRecord(evJoin, s2);
    cudaStreamWaitEvent(0, evJoin, 0);

    // Joined: scale h1 rows, then pipelined agg1 / gemm2 over two node chunks
    k_scale_h1<<<(n * (HID / 8) + 255) / 256, 256>>>(n);

    k_agg1<<<(nh * 32 + 255) / 256, 256>>>(b1, 0, nh);           // chunk 0
    cudaEventRecord(evA, 0);

    cudaStreamWaitEvent(s2, evA, 0);                             // gemm2 chunk 0 || agg1 chunk 1
    {
        dim3 grid(OUT_CH / BN, nh / BM);
        k_gemm2<<<grid, 256, 0, s2>>>(0, n);
    }
    cudaEventRecord(evG2a, s2);

    k_agg1<<<((n - nh) * 32 + 255) / 256, 256>>>(b1, nh, n);     // chunk 1
    {
        dim3 grid(OUT_CH / BN, (n - nh + BM - 1) / BM);
        k_gemm2<<<grid, 256>>>(nh, n);
    }
    cudaStreamWaitEvent(0, evG2a, 0);

    // agg2 (node per 16-lane group) and decode (4 edges/warp)
    k_agg2<<<(n * 16 + 255) / 256, 256>>>(b2, n);
    k_decode<<<(((E + 3) / 4) * 32 + 255) / 256, 256>>>(ei, out, E, n);

    cudaEventDestroy(evFork);
    cudaEventDestroy(evJoin);
    cudaEventDestroy(evA);
    cudaEventDestroy(evG2a);
    cudaStreamDestroy(s2);
}

// round 11
// speedup vs baseline: 2.1683x; 1.0020x over previous
#include <cuda_runtime.h>
#include <cuda_fp16.h>
#include <mma.h>
#include <cstdint>

using namespace nvcuda;

// Problem constants (GAE: GCN encoder x2 + inner-product decoder)
#define NN 50000
#define NE 1600000
#define IN_CH 256
#define HID 256
#define OUT_CH 128
#define GK 256   // K dim of both GEMMs

// ---------------- scratch (static device globals; no allocation) ----------
__device__ __align__(256) int    g_cnt[NN];
__device__ __align__(256) int    g_rowstart[NN + 1];
__device__ __align__(256) int    g_pos[NN];
__device__ __align__(256) float  g_dinv[NN];
__device__ __align__(256) int    g_csr[NE];
__device__ __align__(256) __half g_xh[(size_t)NN * IN_CH];    // fp16 x (unscaled)
__device__ __align__(256) __half g_w1h[GK * HID];             // fp16 W1
__device__ __align__(256) __half g_w2h[GK * OUT_CH];          // fp16 W2
__device__ __align__(256) __half g_h1h[(size_t)NN * HID];     // fp16: x@W1, then *= dinv[row]
__device__ __align__(256) __half g_z1h[(size_t)NN * HID];     // fp16: relu(agg*di+b1)*di
__device__ __align__(256) __half g_h2h[(size_t)NN * OUT_CH];  // fp16: z1h@W2 (rows pre-scaled)
__device__ __align__(256) __half g_z2h[(size_t)NN * OUT_CH];  // fp16: agg*di+b2

// ---------------- degree / CSR build --------------------------------------
__global__ void k_zero_cnt(int n) {
    int i = blockIdx.x * blockDim.x + threadIdx.x;
    if (i < n) g_cnt[i] = 0;
}

__global__ void k_count(const int* __restrict__ ei, int E, int n) {
    int e = blockIdx.x * blockDim.x + threadIdx.x;
    if (e < E) {
        int d = ei[(size_t)E + e];
        if ((unsigned)d < (unsigned)n) atomicAdd(&g_cnt[d], 1);
    }
}

__global__ void k_scan(int n) {
    __shared__ int part[1024];
    int t = threadIdx.x;
    const int CHUNK = (NN + 1023) / 1024;
    int lo = t * CHUNK;
    int hi = lo + CHUNK; if (hi > n) hi = n;
    int s = 0;
    for (int i = lo; i < hi; i++) s += g_cnt[i];
    part[t] = s;
    __syncthreads();
    for (int off = 1; off < 1024; off <<= 1) {
        int v = (t >= off) ? part[t - off] : 0;
        __syncthreads();
        part[t] += v;
        __syncthreads();
    }
    int base = (t == 0) ? 0 : part[t - 1];
    for (int i = lo; i < hi; i++) {
        g_rowstart[i] = base;
        g_pos[i] = base;
        g_dinv[i] = rsqrtf((float)(g_cnt[i] + 1));
        base += g_cnt[i];
    }
    if (t == 0) g_rowstart[n] = part[1023];
}

__global__ void k_fill(const int* __restrict__ ei, int E, int n) {
    int e = blockIdx.x * blockDim.x + threadIdx.x;
    if (e < E) {
        int s = ei[e];
        int d = ei[(size_t)E + e];
        if ((unsigned)s < (unsigned)n && (unsigned)d < (unsigned)n) {
            int p = atomicAdd(&g_pos[d], 1);
            if ((unsigned)p < (unsigned)NE) g_csr[p] = s;
        }
    }
}

// ---------------- conversions (no dinv dependency -> overlappable) --------
__device__ __forceinline__ void cvt_chunk(const float* __restrict__ S,
                                          __half* __restrict__ D, int i) {
    float4 v = __ldg((const float4*)S + i);
    __half2 lo = __floats2half2_rn(v.x, v.y);
    __half2 hi = __floats2half2_rn(v.z, v.w);
    uint2 o; o.x = *(unsigned*)&lo; o.y = *(unsigned*)&hi;
    *((uint2*)D + i) = o;
}

__global__ void k_cvt_x(const float* __restrict__ x, int n) {
    int i = blockIdx.x * blockDim.x + threadIdx.x;
    if (i < n * (IN_CH / 4)) cvt_chunk(x, g_xh, i);
}

__global__ void k_cvt_w(const float* __restrict__ W1, const float* __restrict__ W2) {
    int i = blockIdx.x * blockDim.x + threadIdx.x;
    const int C1 = GK * HID / 4;
    const int C2 = GK * OUT_CH / 4;
    if (i < C1) cvt_chunk(W1, g_w1h, i);
    else if (i < C1 + C2) cvt_chunk(W2, g_w2h, i - C1);
}

// post-join: h1h[row,:] *= dinv[row]
__global__ void k_scale_h1(int n) {
    int i = blockIdx.x * blockDim.x + threadIdx.x;   // one uint4 (8 halves)
    int total = n * (HID / 8);
    if (i >= total) return;
    float di = g_dinv[i / (HID / 8)];
    uint4 v = *((const uint4*)g_h1h + i);
    __half2* p = (__half2*)&v;
#pragma unroll
    for (int j = 0; j < 4; j++) {
        float2 f = __half22float2(p[j]);
        p[j] = __floats2half2_rn(f.x * di, f.y * di);
    }
    *((uint4*)g_h1h + i) = v;
}

// ---------------- wmma fp16 GEMM: C = A[M,256] @ B[256,Ncols] --------------
#define BM 128
#define BN 64
#define BK 32
#define A_LD 40   // BK + 8 pad (halves)
#define B_LD 72   // BN + 8 pad (halves)
#define C_LD 68   // BN + 4 pad (floats)

__device__ __forceinline__ void gemm_wmma_body(
    const __half* __restrict__ A, const __half* __restrict__ B,
    __half* __restrict__ C, int rowBase, int M, int Ncols)
{
    __shared__ __align__(16) char sm[BM * C_LD * 4];   // 34816 B; unioned A/B vs C
    __half* As = (__half*)sm;                          // [BM][A_LD]
    __half* Bs = As + BM * A_LD;                       // [BK][B_LD]
    float*  Cs = (float*)sm;                           // [BM][C_LD]

    int tid = threadIdx.x;
    int warp = tid >> 5;
    int wrow = warp >> 1;
    int wcol = warp & 1;
    int row0 = rowBase + blockIdx.y * BM;
    int col0 = blockIdx.x * BN;

    wmma::fragment<wmma::accumulator, 16, 16, 16, float> c[2][2];
#pragma unroll
    for (int i = 0; i < 2; i++)
#pragma unroll
        for (int j = 0; j < 2; j++) wmma::fill_fragment(c[i][j], 0.f);

    for (int k0 = 0; k0 < GK; k0 += BK) {
#pragma unroll
        for (int t = 0; t < 2; t++) {
            int v = tid + t * 256;
            int r = v >> 2;
            int kc = (v & 3) * 8;
            int grow = row0 + r;
            uint4 val = make_uint4(0u, 0u, 0u, 0u);
            if (grow < M)
                val = *(const uint4*)(A + (size_t)grow * GK + k0 + kc);
            *(uint4*)(As + r * A_LD + kc) = val;
        }
        {
            int r = tid >> 3;
            int c8 = (tid & 7) * 8;
            uint4 val = *(const uint4*)(B + (size_t)(k0 + r) * Ncols + col0 + c8);
            *(uint4*)(Bs + r * B_LD + c8) = val;
        }
        __syncthreads();

#pragma unroll
        for (int kk = 0; kk < BK; kk += 16) {
            wmma::fragment<wmma::matrix_a, 16, 16, 16, __half, wmma::row_major> a[2];
            wmma::fragment<wmma::matrix_b, 16, 16, 16, __half, wmma::row_major> b[2];
#pragma unroll
            for (int i = 0; i < 2; i++)
                wmma::load_matrix_sync(a[i], As + (wrow * 32 + i * 16) * A_LD + kk, A_LD);
#pragma unroll
            for (int j = 0; j < 2; j++)
                wmma::load_matrix_sync(b[j], Bs + kk * B_LD + wcol * 32 + j * 16, B_LD);
#pragma unroll
            for (int i = 0; i < 2; i++)
#pragma unroll
                for (int j = 0; j < 2; j++)
                    wmma::mma_sync(c[i][j], a[i], b[j], c[i][j]);
        }
        __syncthreads();
    }

#pragma unroll
    for (int i = 0; i < 2; i++)
#pragma unroll
        for (int j = 0; j < 2; j++)
            wmma::store_matrix_sync(Cs + (wrow * 32 + i * 16) * C_LD + wcol * 32 + j * 16,
                                    c[i][j], C_LD, wmma::mem_row_major);
    __syncthreads();

    if (tid < BM) {
        int grow = row0 + tid;
        if (grow < M) {
            const float* src = Cs + tid * C_LD;
            __half* dst = C + (size_t)grow * Ncols + col0;
#pragma unroll
            for (int cB = 0; cB < BN; cB += 8) {
                __half2 p0 = __floats2half2_rn(src[cB + 0], src[cB + 1]);
                __half2 p1 = __floats2half2_rn(src[cB + 2], src[cB + 3]);
                __half2 p2 = __floats2half2_rn(src[cB + 4], src[cB + 5]);
                __half2 p3 = __floats2half2_rn(src[cB + 6], src[cB + 7]);
                uint4 o;
                o.x = *(unsigned*)&p0; o.y = *(unsigned*)&p1;
                o.z = *(unsigned*)&p2; o.w = *(unsigned*)&p3;
                *(uint4*)(dst + cB) = o;
            }
        }
    }
}

__global__ __launch_bounds__(256) void k_gemm1(int M) {
    gemm_wmma_body(g_xh, g_w1h, g_h1h, 0, M, HID);
}

__global__ __launch_bounds__(256) void k_gemm2(int rowBase, int M) {
    gemm_wmma_body(g_z1h, g_w2h, g_h2h, rowBase, M, OUT_CH);
}

// ---------------- CSR aggregation (pure row-sum; rows pre-scaled) ----------
__device__ __forceinline__ void acc8_add(float* acc, uint4 v) {
    const __half2* p = (const __half2*)&v;
#pragma unroll
    for (int j = 0; j < 4; j++) {
        float2 f = __half22float2(p[j]);
        acc[2 * j]     += f.x;
        acc[2 * j + 1] += f.y;
    }
}

// agg1 over node range [base, limit): one warp/node.
// Index staging: one coalesced csr load per 32 edges; neighbors broadcast via shfl.
__global__ __launch_bounds__(256) void k_agg1(const float* __restrict__ bias,
                                              int base, int limit)
{
    int node = base + ((blockIdx.x * blockDim.x + threadIdx.x) >> 5);
    if (node >= limit) return;
    int lane = threadIdx.x & 31;
    const unsigned FULL = 0xffffffffu;

    float acc[8] = {0.f, 0.f, 0.f, 0.f, 0.f, 0.f, 0.f, 0.f};
    acc8_add(acc, __ldg((const uint4*)(g_h1h + (size_t)node * HID) + lane));

    int beg = g_rowstart[node];
    int end = g_rowstart[node + 1];
    for (int i0 = beg; i0 < end; i0 += 32) {
        int cnt = end - i0; if (cnt > 32) cnt = 32;
        int myidx = (i0 + lane < end) ? g_csr[i0 + lane] : 0;
        int j = 0;
        for (; j + 8 <= cnt; j += 8) {
            int nb[8];
#pragma unroll
            for (int u = 0; u < 8; u++) nb[u] = __shfl_sync(FULL, myidx, j + u);
            uint4 v[8];
#pragma unroll
            for (int u = 0; u < 8; u++)
                v[u] = __ldg((const uint4*)(g_h1h + (size_t)nb[u] * HID) + lane);
#pragma unroll
            for (int u = 0; u < 8; u++) acc8_add(acc, v[u]);
        }
        for (; j < cnt; j++) {
            int nb = __shfl_sync(FULL, myidx, j);
            acc8_add(acc, __ldg((const uint4*)(g_h1h + (size_t)nb * HID) + lane));
        }
    }

    float di = g_dinv[node];
    float4 b0 = __ldg((const float4*)bias + lane * 2);
    float4 b1v = __ldg((const float4*)bias + lane * 2 + 1);
    float o[8];
    o[0] = fmaxf(acc[0] * di + b0.x, 0.f) * di;
    o[1] = fmaxf(acc[1] * di + b0.y, 0.f) * di;
    o[2] = fmaxf(acc[2] * di + b0.z, 0.f) * di;
    o[3] = fmaxf(acc[3] * di + b0.w, 0.f) * di;
    o[4] = fmaxf(acc[4] * di + b1v.x, 0.f) * di;
    o[5] = fmaxf(acc[5] * di + b1v.y, 0.f) * di;
    o[6] = fmaxf(acc[6] * di + b1v.z, 0.f) * di;
    o[7] = fmaxf(acc[7] * di + b1v.w, 0.f) * di;
    __half2 h0 = __floats2half2_rn(o[0], o[1]);
    __half2 h1 = __floats2half2_rn(o[2], o[3]);
    __half2 h2 = __floats2half2_rn(o[4], o[5]);
    __half2 h3 = __floats2half2_rn(o[6], o[7]);
    uint4 ov;
    ov.x = *(unsigned*)&h0; ov.y = *(unsigned*)&h1;
    ov.z = *(unsigned*)&h2; ov.w = *(unsigned*)&h3;
    *((uint4*)(g_z1h + (size_t)node * HID) + lane) = ov;
}

// agg2: one node per 16-lane group; group-local shfl (two groups per warp diverge).
__global__ __launch_bounds__(256) void k_agg2(const float* __restrict__ bias, int n)
{
    int node = (blockIdx.x * blockDim.x + threadIdx.x) >> 4;
    if (node >= n) return;
    int lane = threadIdx.x & 31;
    int grp  = lane >> 4;
    int l16  = lane & 15;
    unsigned GM = 0xFFFFu << (grp * 16);

    float acc[8] = {0.f, 0.f, 0.f, 0.f, 0.f, 0.f, 0.f, 0.f};
    acc8_add(acc, __ldg((const uint4*)(g_h2h + (size_t)node * OUT_CH) + l16));

    int beg = g_rowstart[node];
    int end = g_rowstart[node + 1];
    for (int i0 = beg; i0 < end; i0 += 16) {
        int cnt = end - i0; if (cnt > 16) cnt = 16;
        int myidx = (i0 + l16 < end) ? g_csr[i0 + l16] : 0;
        int j = 0;
        for (; j + 8 <= cnt; j += 8) {
            int nb[8];
#pragma unroll
            for (int u = 0; u < 8; u++) nb[u] = __shfl_sync(GM, myidx, j + u, 16);
            uint4 v[8];
#pragma unroll
            for (int u = 0; u < 8; u++)
                v[u] = __ldg((const uint4*)(g_h2h + (size_t)nb[u] * OUT_CH) + l16);
#pragma unroll
            for (int u = 0; u < 8; u++) acc8_add(acc, v[u]);
        }
        for (; j < cnt; j++) {
            int nb = __shfl_sync(GM, myidx, j, 16);
            acc8_add(acc, __ldg((const uint4*)(g_h2h + (size_t)nb * OUT_CH) + l16));
        }
    }

    float di = g_dinv[node];
    float4 b0 = __ldg((const float4*)bias + l16 * 2);
    float4 b1v = __ldg((const float4*)bias + l16 * 2 + 1);
    __half2 h0 = __floats2half2_rn(acc[0] * di + b0.x,  acc[1] * di + b0.y);
    __half2 h1 = __floats2half2_rn(acc[2] * di + b0.z,  acc[3] * di + b0.w);
    __half2 h2 = __floats2half2_rn(acc[4] * di + b1v.x, acc[5] * di + b1v.y);
    __half2 h3 = __floats2half2_rn(acc[6] * di + b1v.z, acc[7] * di + b1v.w);
    uint4 ov;
    ov.x = *(unsigned*)&h0; ov.y = *(unsigned*)&h1;
    ov.z = *(unsigned*)&h2; ov.w = *(unsigned*)&h3;
    *((uint4*)(g_z2h + (size_t)node * OUT_CH) + l16) = ov;
}

// ---------------- decoder: 4 edges per 16-lane group (8 per warp) ----------
__global__ __launch_bounds__(256) void k_decode(
    const int* __restrict__ ei, float* __restrict__ out, int E, int n)
{
    int warp = (blockIdx.x * blockDim.x + threadIdx.x) >> 5;
    int lane = threadIdx.x & 31;
    int grp  = lane >> 4;
    int l16  = lane & 15;
    int e0 = warp * 8 + grp * 4;   // this group's four edges
    if (e0 >= E) return;

    uint4 va[4], vb[4];
    bool ok[4];
#pragma unroll
    for (int u = 0; u < 4; u++) {
        int e = e0 + u;
        bool has = (e < E);
        int s = has ? __ldg(&ei[e]) : 0;
        int d = has ? __ldg(&ei[(size_t)E + e]) : 0;
        ok[u] = has && (unsigned)s < (unsigned)n && (unsigned)d < (unsigned)n;
        va[u] = make_uint4(0, 0, 0, 0);
        vb[u] = make_uint4(0, 0, 0, 0);
        if (ok[u]) {
            va[u] = __ldg((const uint4*)(g_z2h + (size_t)s * OUT_CH) + l16);
            vb[u] = __ldg((const uint4*)(g_z2h + (size_t)d * OUT_CH) + l16);
        }
    }

    float p[4];
#pragma unroll
    for (int u = 0; u < 4; u++) {
        const __half2* pa = (const __half2*)&va[u];
        const __half2* pb = (const __half2*)&vb[u];
        float acc = 0.f;
#pragma unroll
        for (int j = 0; j < 4; j++) {
            float2 a = __half22float2(pa[j]);
            float2 b = __half22float2(pb[j]);
            acc += a.x * b.x + a.y * b.y;
        }
        p[u] = acc;
    }
#pragma unroll
    for (int off = 8; off > 0; off >>= 1) {
#pragma unroll
        for (int u = 0; u < 4; u++)
            p[u] += __shfl_down_sync(0xffffffffu, p[u], off, 16);
    }
    if (l16 == 0) {
#pragma unroll
        for (int u = 0; u < 4; u++)
            if (e0 + u < E) out[e0 + u] = p[u];
    }
}

// ---------------- launch ---------------------------------------------------
extern "C" void kernel_launch(void* const* d_in, const int* in_sizes, int n_in,
                              void* d_out, int out_size)
{
    const float* x  = (const float*)d_in[0];
    const int*   ei = (const int*)d_in[1];   // [2, E] indices, staged as int32
    const float* W1 = (const float*)d_in[2];
    const float* b1 = (const float*)d_in[3];
    const float* W2 = (const float*)d_in[4];
    const float* b2 = (const float*)d_in[5];
    float* out = (float*)d_out;

    int n = in_sizes[0] / IN_CH;    // 50000
    int E = in_sizes[1] / 2;        // 1600000
    int nh = ((n / 2 + BM - 1) / BM) * BM;   // chunk split, BM-aligned
    if (nh > n) nh = n;

    // Streams/events: capture-legal fork/join; runs only at capture time.
    cudaStream_t s2;
    cudaStreamCreate(&s2);
    cudaEvent_t evFork, evJoin, evA, evG2a;
    cudaEventCreateWithFlags(&evFork, cudaEventDisableTiming);
    cudaEventCreateWithFlags(&evJoin, cudaEventDisableTiming);
    cudaEventCreateWithFlags(&evA, cudaEventDisableTiming);
    cudaEventCreateWithFlags(&evG2a, cudaEventDisableTiming);

    cudaEventRecord(evFork, 0);
    cudaStreamWaitEvent(s2, evFork, 0);

    // Branch A (default stream): CSR build (atomics / ALU bound)
    k_zero_cnt<<<(n + 255) / 256, 256>>>(n);
    k_count<<<(E + 255) / 256, 256>>>(ei, E, n);
    k_scan<<<1, 1024>>>(n);
    k_fill<<<(E + 255) / 256, 256>>>(ei, E, n);

    // Branch B (s2): fp16 conversions + GEMM1 (tensor / L2 bound)
    k_cvt_x<<<(n * (IN_CH / 4) + 255) / 256, 256, 0, s2>>>(x, n);
    k_cvt_w<<<((GK * HID + GK * OUT_CH) / 4 + 255) / 256, 256, 0, s2>>>(W1, W2);
    {
        dim3 grid(HID / BN, (n + BM - 1) / BM);
        k_gemm1<<<grid, 256, 0, s2>>>(n);
    }
    cudaEventRecord(evJoin, s2);
    cudaStreamWaitEvent(0, evJoin, 0);

    // Joined: scale h1 rows, then pipelined agg1 / gemm2 over two node chunks
    k_scale_h1<<<(n * (HID / 8) + 255) / 256, 256>>>(n);

    k_agg1<<<(nh * 32 + 255) / 256, 256>>>(b1, 0, nh);           // chunk 0
    cudaEventRecord(evA, 0);

    cudaStreamWaitEvent(s2, evA, 0);                             // gemm2 chunk 0 || agg1 chunk 1
    {
        dim3 grid(OUT_CH / BN, nh / BM);
        k_gemm2<<<grid, 256, 0, s2>>>(0, n);
    }
    cudaEventRecord(evG2a, s2);

    k_agg1<<<((n - nh) * 32 + 255) / 256, 256>>>(b1, nh, n);     // chunk 1
    {
        dim3 grid(OUT_CH / BN, (n - nh + BM - 1) / BM);
        k_gemm2<<<grid, 256>>>(nh, n);
    }
    cudaStreamWaitEvent(0, evG2a, 0);

    // agg2 (node per 16-lane group) and decode (8 edges/warp)
    k_agg2<<<(n * 16 + 255) / 256, 256>>>(b2, n);
    k_decode<<<(((E + 7) / 8) * 32 + 255) / 256, 256>>>(ei, out, E, n);

    cudaEventDestroy(evFork);
    cudaEventDestroy(evJoin);
    cudaEventDestroy(evA);
    cudaEventDestroy(evG2a);
    cudaStreamDestroy(s2);
}